// round 7
// baseline (speedup 1.0000x reference)
#include <cuda_runtime.h>
#include <cuda_fp16.h>
#include <math.h>
#include <stdint.h>

// Problem constants
#define B   256
#define Hd  1024
#define L   400
#define V   50257
#define NTV 393              // ceil(V/128)

#define OUT_H    ((long)B * V)
#define OUT_AW   ((long)B * V + (long)B * Hd)

// ---------------- scratch (device globals) ---------------------------------
__device__ float g_scores[B * L];
__device__ float g_attn[B * Hd];
__device__ float g_o[B * Hd];
__device__ float g_logits[(long)B * V];
__device__ float g_part[4L * B * 3 * Hd];     // split-K partials (12.6 MB) — sized for fused GRU [4][B][3H]
__device__ float g_rmax[(long)NTV * B];
__device__ float g_rsum[(long)NTV * B];
__device__ float g_lse[B];

// ---------------- helpers ---------------------------------------------------
__device__ __forceinline__ uint32_t smem_u32(const void* p) {
    uint32_t a;
    asm("{ .reg .u64 t; cvta.to.shared.u64 t, %1; cvt.u32.u64 %0, t; }" : "=r"(a) : "l"(p));
    return a;
}

__device__ __forceinline__ uint32_t h2bits(float x, float y) {
    __half2 h = __floats2half2_rn(x, y);
    return *(uint32_t*)&h;
}

#define SWZ128(x) ((x) ^ (((x) >> 3) & 0x70))

__device__ __forceinline__ void ldsm_x4(uint32_t* r, uint32_t addr) {
    asm volatile("ldmatrix.sync.aligned.m8n8.x4.shared.b16 {%0,%1,%2,%3}, [%4];"
                 : "=r"(r[0]), "=r"(r[1]), "=r"(r[2]), "=r"(r[3]) : "r"(addr));
}

__device__ __forceinline__ void mma_f16(float* c, const uint32_t* a, const uint32_t* b) {
    asm volatile(
        "mma.sync.aligned.m16n8k16.row.col.f32.f16.f16.f32 "
        "{%0,%1,%2,%3}, {%4,%5,%6,%7}, {%8,%9}, {%0,%1,%2,%3};"
        : "+f"(c[0]), "+f"(c[1]), "+f"(c[2]), "+f"(c[3])
        : "r"(a[0]), "r"(a[1]), "r"(a[2]), "r"(a[3]), "r"(b[0]), "r"(b[1]));
}

// fast exp (full-rate FFMA path)
__device__ __forceinline__ float fexp(float x)
{
    float t = fmaxf(x * 1.44269504f, -125.0f);
    float fi = t + 12582912.f;
    int   i = __float_as_int(fi);
    float fr = t - (fi - 12582912.f);
    float y = fr * 0.69314718f;
    float p = fmaf(y, 0.25f, 1.f);
    p = fmaf(y * p, 0.33333333f, 1.f);
    p = fmaf(y * p, 0.5f, 1.f);
    p = fmaf(y, p, 1.f);
    return __int_as_float((i + (127 - 0x4B400000)) << 23) * p;
}

// ---------------- fp16 tensor-core GEMM (R4 engine + fusions) ---------------
// C[256,N] = concat_K(A1[.,0:KA1], A2[.,KA1:K]) @ Bop (+bias)
// TRANSB=1: Bop = W[N,K]^T.  TRANSB=0: Bop = W[K,N] row-major.
// grid.y = 2 (128 rows per CTA). Split-K via blockIdx.z (chunkK); partials at
// C + z*256*N. direct=1: apply bias (+relu) and write final C.
// If rmax != null (logits mode): also emit per-tile row (max, expsum).
// Block tile 128x128x64, 256 threads, 8 warps (2m x 4n), warp tile 64x32.
#define GH_SMEM 65536

template<int TRANSB>
__global__ __launch_bounds__(256, 1) void gemm_h16(
    const float* __restrict__ A1, const float* __restrict__ A2, int KA1,
    const float* __restrict__ W, const float* __restrict__ bias,
    float* __restrict__ C, float* __restrict__ rmax, float* __restrict__ rsum,
    int N, int K, int chunkK, int relu, int direct)
{
    extern __shared__ char smem[];
    const uint32_t sb = smem_u32(smem);

    const int t = threadIdx.x;
    const int lane = t & 31;
    const int wid = t >> 5;
    const int wm = wid >> 2;       // 0..1
    const int wn = wid & 3;        // 0..3
    const int g = lane >> 2;       // 0..7
    const int q = lane & 3;        // 0..3

    const int m0 = blockIdx.y * 128;
    const int n0 = blockIdx.x * 128;
    const int kstart = blockIdx.z * chunkK;
    const int kend = min(kstart + chunkK, K);
    const int KA2 = K - KA1;

    const int arow = t >> 4;          // 0..15 (+16*i)
    const int acol = (t & 15) * 4;    // float col 0..60

    float4 ra[8], rb[8];
    float4 rba[4], rbb[4];

    float acc[4][4][4];
    #pragma unroll
    for (int i = 0; i < 4; i++)
        #pragma unroll
        for (int j = 0; j < 4; j++)
            #pragma unroll
            for (int v = 0; v < 4; v++) acc[i][j][v] = 0.f;

    auto loadA = [&](int k0) {
        #pragma unroll
        for (int i = 0; i < 8; i++) {
            int m = m0 + arow + 16 * i;
            int k = k0 + acol;
            ra[i] = make_float4(0.f, 0.f, 0.f, 0.f);
            if (k < kend) {
                if (k < KA1) ra[i] = *(const float4*)&A1[(long)m * KA1 + k];
                else         ra[i] = *(const float4*)&A2[(long)m * KA2 + (k - KA1)];
            }
        }
    };
    auto loadB = [&](int k0) {
        if (TRANSB) {
            #pragma unroll
            for (int i = 0; i < 8; i++) {
                int n = n0 + arow + 16 * i;
                int k = k0 + acol;
                rb[i] = make_float4(0.f, 0.f, 0.f, 0.f);
                if (n < N && k < kend) rb[i] = *(const float4*)&W[(long)n * K + k];
            }
        } else {
            #pragma unroll
            for (int i = 0; i < 4; i++) {
                int cell = t + i * 256;
                int kp = cell >> 5;         // 0..31
                int nq = cell & 31;         // 0..31
                int k = k0 + 2 * kp;
                int n = n0 + nq * 4;
                rba[i] = make_float4(0.f, 0.f, 0.f, 0.f);
                rbb[i] = make_float4(0.f, 0.f, 0.f, 0.f);
                if (k < kend && n < N) {
                    rba[i] = *(const float4*)&W[(long)k * N + n];
                    if (k + 1 < kend) rbb[i] = *(const float4*)&W[(long)(k + 1) * N + n];
                }
            }
        }
    };
    auto storeAB = [&](int s) {
        char* Ab = smem + s * 32768;
        char* Bb = smem + s * 32768 + 16384;
        #pragma unroll
        for (int i = 0; i < 8; i++) {
            int row = arow + 16 * i;
            uint32_t off = SWZ128((uint32_t)(row * 128 + acol * 2));
            *(uint2*)(Ab + off) = make_uint2(h2bits(ra[i].x, ra[i].y), h2bits(ra[i].z, ra[i].w));
        }
        if (TRANSB) {
            #pragma unroll
            for (int i = 0; i < 8; i++) {
                int row = arow + 16 * i;
                uint32_t off = SWZ128((uint32_t)(row * 128 + acol * 2));
                *(uint2*)(Bb + off) = make_uint2(h2bits(rb[i].x, rb[i].y), h2bits(rb[i].z, rb[i].w));
            }
        } else {
            #pragma unroll
            for (int i = 0; i < 4; i++) {
                int cell = t + i * 256;
                int kp = cell >> 5;
                int nq = cell & 31;
                const float* fa = (const float*)&rba[i];
                const float* fb = (const float*)&rbb[i];
                #pragma unroll
                for (int j = 0; j < 4; j++) {
                    int row = nq * 4 + j;
                    uint32_t off = SWZ128((uint32_t)(row * 128 + kp * 4));
                    *(uint32_t*)(Bb + off) = h2bits(fa[j], fb[j]);
                }
            }
        }
    };

    const int a_row = lane & 15;
    const int a_cb = (lane >> 4) << 4;
    const int b_row = (lane & 7) + ((lane >> 4) << 3);
    const int b_cb = ((lane >> 3) & 1) << 4;

    auto compute = [&](int s) {
        const uint32_t Ab = sb + s * 32768;
        const uint32_t Bb = Ab + 16384;
        #pragma unroll
        for (int ks = 0; ks < 4; ks++) {
            uint32_t af[4][4], bf[2][4];
            #pragma unroll
            for (int mt = 0; mt < 4; mt++) {
                int r = wm * 64 + mt * 16 + a_row;
                ldsm_x4(af[mt], Ab + SWZ128((uint32_t)(r * 128 + ks * 32 + a_cb)));
            }
            #pragma unroll
            for (int np = 0; np < 2; np++) {
                int r = wn * 32 + np * 16 + b_row;
                ldsm_x4(bf[np], Bb + SWZ128((uint32_t)(r * 128 + ks * 32 + b_cb)));
            }
            #pragma unroll
            for (int mt = 0; mt < 4; mt++)
                #pragma unroll
                for (int nt = 0; nt < 4; nt++)
                    mma_f16(acc[mt][nt], af[mt], &bf[nt >> 1][(nt & 1) * 2]);
        }
    };

    const int ntiles = (kend - kstart + 63) / 64;

    loadA(kstart); loadB(kstart);
    storeAB(0);
    __syncthreads();
    for (int c = 1; c < ntiles; c++) {
        loadA(kstart + c * 64); loadB(kstart + c * 64);
        compute((c - 1) & 1);
        __syncthreads();
        storeAB(c & 1);
        __syncthreads();
    }
    compute((ntiles - 1) & 1);

    // ---- epilogue: bias/relu into acc, write C ----
    float* Cw = direct ? C : (C + (long)blockIdx.z * 256 * N);
    #pragma unroll
    for (int mt = 0; mt < 4; mt++) {
        int row = m0 + wm * 64 + mt * 16 + g;
        #pragma unroll
        for (int nt = 0; nt < 4; nt++) {
            int col = n0 + wn * 32 + nt * 8 + 2 * q;
            if (direct) {
                float b0 = (col < N) ? bias[col] : 0.f;
                float b1 = (col + 1 < N) ? bias[col + 1] : 0.f;
                acc[mt][nt][0] += b0; acc[mt][nt][1] += b1;
                acc[mt][nt][2] += b0; acc[mt][nt][3] += b1;
                if (relu) {
                    #pragma unroll
                    for (int v = 0; v < 4; v++) acc[mt][nt][v] = fmaxf(acc[mt][nt][v], 0.f);
                }
            }
            if (col < N)     Cw[(long)row * N + col]           = acc[mt][nt][0];
            if (col + 1 < N) Cw[(long)row * N + col + 1]       = acc[mt][nt][1];
            if (col < N)     Cw[(long)(row + 8) * N + col]     = acc[mt][nt][2];
            if (col + 1 < N) Cw[(long)(row + 8) * N + col + 1] = acc[mt][nt][3];
        }
    }

    // ---- fused log-softmax partials (logits mode; uniform branch) ----
    if (rmax != nullptr) {
        float* redm = (float*)smem;          // [4][128]
        float* reds = redm + 512;
        __syncthreads();                     // stages dead now
        #pragma unroll
        for (int mt = 0; mt < 4; mt++) {
            #pragma unroll
            for (int half = 0; half < 2; half++) {
                float mv = -1e30f;
                float vals[8];
                #pragma unroll
                for (int nt = 0; nt < 4; nt++) {
                    #pragma unroll
                    for (int k2 = 0; k2 < 2; k2++) {
                        int col = n0 + wn * 32 + nt * 8 + 2 * q + k2;
                        float v = (col < N) ? acc[mt][nt][half * 2 + k2] : -1e30f;
                        vals[nt * 2 + k2] = v;
                        mv = fmaxf(mv, v);
                    }
                }
                float sv = 0.f;
                #pragma unroll
                for (int j = 0; j < 8; j++) sv += fexp(vals[j] - mv);
                #pragma unroll
                for (int off = 1; off <= 2; off <<= 1) {
                    float mo = __shfl_xor_sync(0xffffffff, mv, off);
                    float so = __shfl_xor_sync(0xffffffff, sv, off);
                    float mn = fmaxf(mv, mo);
                    sv = sv * fexp(mv - mn) + so * fexp(mo - mn);
                    mv = mn;
                }
                if (q == 0) {
                    int rloc = wm * 64 + mt * 16 + g + half * 8;   // 0..127
                    redm[wn * 128 + rloc] = mv;
                    reds[wn * 128 + rloc] = sv;
                }
            }
        }
        __syncthreads();
        if (t < 128) {
            float m = -1e30f, s = 0.f;
            #pragma unroll
            for (int w = 0; w < 4; w++) {
                float mw = redm[w * 128 + t], sw = reds[w * 128 + t];
                float mn = fmaxf(m, mw);
                s = s * fexp(m - mn) + sw * fexp(mw - mn);
                m = mn;
            }
            rmax[(long)blockIdx.x * 256 + m0 + t] = m;
            rsum[(long)blockIdx.x * 256 + m0 + t] = s;
        }
    }
}

// ---------------- split-K reduce (+bias, +relu) — deterministic -------------
__global__ void reduce_bias(const float* __restrict__ part, const float* __restrict__ bias,
                            float* __restrict__ out, int MN, int N, int SK, int relu)
{
    int idx = blockIdx.x * blockDim.x + threadIdx.x;
    if (idx >= MN) return;
    float s = 0.f;
    for (int c = 0; c < SK; c++) s += part[(long)c * MN + idx];
    if (bias) s += bias[idx % N];
    if (relu) s = fmaxf(s, 0.f);
    out[idx] = s;
}

// ---------------- fused GRU: split-K reduce of gi/gh + gates ----------------
__global__ void gru_fuse(const float* __restrict__ part, const float* __restrict__ hidden,
                         const float* __restrict__ bih, const float* __restrict__ bhh,
                         float* __restrict__ h_new)
{
    int idx = blockIdx.x * blockDim.x + threadIdx.x;
    if (idx >= B * Hd) return;
    int b = idx / Hd, j = idx - b * Hd;
    const long NN = 3 * Hd;
    const long MN = (long)B * NN;
    const float* giA = part;            // [2][B][3H]
    const float* ghA = part + 2 * MN;   // [2][B][3H]
    long base = (long)b * NN + j;

    float ir = giA[base] + giA[MN + base] + bih[j];
    float iz = giA[base + Hd] + giA[MN + base + Hd] + bih[j + Hd];
    float in_ = giA[base + 2 * Hd] + giA[MN + base + 2 * Hd] + bih[j + 2 * Hd];
    float hr = ghA[base] + ghA[MN + base] + bhh[j];
    float hz = ghA[base + Hd] + ghA[MN + base + Hd] + bhh[j + Hd];
    float hn = ghA[base + 2 * Hd] + ghA[MN + base + 2 * Hd] + bhh[j + 2 * Hd];

    float r = 1.f / (1.f + expf(-(ir + hr)));
    float z = 1.f / (1.f + expf(-(iz + hz)));
    float nn = tanhf(in_ + r * hn);
    h_new[idx] = (1.f - z) * nn + z * hidden[idx];
}

// ---------------- warp-per-row softmax (L=400) -------------------------------
__global__ void softmax_warp(const float* __restrict__ in, float* __restrict__ out, int n)
{
    int w = (blockIdx.x * blockDim.x + threadIdx.x) >> 5;
    int lid = threadIdx.x & 31;
    if (w >= B) return;
    const float* x = in + (long)w * n;
    float* y = out + (long)w * n;

    float m = -1e30f;
    for (int i = lid; i < n; i += 32) m = fmaxf(m, x[i]);
    #pragma unroll
    for (int o = 16; o > 0; o >>= 1) m = fmaxf(m, __shfl_xor_sync(0xffffffff, m, o));
    float s = 0.f;
    for (int i = lid; i < n; i += 32) s += fexp(x[i] - m);
    #pragma unroll
    for (int o = 16; o > 0; o >>= 1) s += __shfl_xor_sync(0xffffffff, s, o);
    float inv = 1.f / s;
    for (int i = lid; i < n; i += 32) y[i] = fexp(x[i] - m) * inv;
}

// ---------------- lse reduce over tiles --------------------------------------
__global__ void lse_reduce(const float* __restrict__ rmax, const float* __restrict__ rsum,
                           float* __restrict__ lse)
{
    int t = threadIdx.x;   // 256
    float m = -1e30f, s = 0.f;
    for (int tile = 0; tile < NTV; tile++) {
        float mw = rmax[(long)tile * 256 + t];
        float sw = rsum[(long)tile * 256 + t];
        float mn = fmaxf(m, mw);
        s = s * fexp(m - mn) + sw * fexp(mw - mn);
        m = mn;
    }
    lse[t] = m + logf(s);
}

// ---------------- final: logp = logits - lse ---------------------------------
__global__ void logp_final(const float* __restrict__ logits, const float* __restrict__ lse,
                           float* __restrict__ out)
{
    int col = blockIdx.x * 1024 + threadIdx.x;
    int row = blockIdx.y;
    if (col < V) {
        long i = (long)row * V + col;
        out[i] = logits[i] - lse[row];
    }
}

// ---------------- launch -----------------------------------------------------
extern "C" void kernel_launch(void* const* d_in, const int* in_sizes, int n_in,
                              void* d_out, int out_size)
{
    const float* embedded = (const float*)d_in[0];
    const float* hidden   = (const float*)d_in[1];
    const float* enc      = (const float*)d_in[2];
    const float* attn_W   = (const float*)d_in[3];
    const float* attn_b   = (const float*)d_in[4];
    const float* comb_W   = (const float*)d_in[5];
    const float* comb_b   = (const float*)d_in[6];
    const float* gru_Wih  = (const float*)d_in[7];
    const float* gru_Whh  = (const float*)d_in[8];
    const float* gru_bih  = (const float*)d_in[9];
    const float* gru_bhh  = (const float*)d_in[10];
    const float* out_W    = (const float*)d_in[11];
    const float* out_b    = (const float*)d_in[12];

    float* out = (float*)d_out;
    float* out_logp = out;
    float* out_h    = out + OUT_H;
    float* out_aw   = out + OUT_AW;

    float *scores, *attn, *o, *logits, *part, *rmax, *rsum, *lse;
    cudaGetSymbolAddress((void**)&scores, g_scores);
    cudaGetSymbolAddress((void**)&attn, g_attn);
    cudaGetSymbolAddress((void**)&o, g_o);
    cudaGetSymbolAddress((void**)&logits, g_logits);
    cudaGetSymbolAddress((void**)&part, g_part);
    cudaGetSymbolAddress((void**)&rmax, g_rmax);
    cudaGetSymbolAddress((void**)&rsum, g_rsum);
    cudaGetSymbolAddress((void**)&lse, g_lse);

    cudaFuncSetAttribute(gemm_h16<1>, cudaFuncAttributeMaxDynamicSharedMemorySize, GH_SMEM);
    cudaFuncSetAttribute(gemm_h16<0>, cudaFuncAttributeMaxDynamicSharedMemorySize, GH_SMEM);

    // 1. scores = [x|h] @ attn_W^T (+attn_b), split-K=8
    gemm_h16<1><<<dim3(4, 2, 8), 256, GH_SMEM>>>(embedded, hidden, Hd, attn_W, nullptr,
                                                 part, nullptr, nullptr,
                                                 L, 2 * Hd, 256, 0, 0);
    reduce_bias<<<(B * L + 255) / 256, 256>>>(part, attn_b, scores, B * L, L, 8, 0);

    // 2. attn_weights = softmax(scores) -> out_aw
    softmax_warp<<<32, 256>>>(scores, out_aw, L);

    // 3. attn_applied = attn_weights @ enc (NN), split-K=4
    gemm_h16<0><<<dim3(8, 2, 4), 256, GH_SMEM>>>(out_aw, nullptr, L, enc, nullptr,
                                                 part, nullptr, nullptr,
                                                 Hd, L, 128, 0, 0);
    reduce_bias<<<(B * Hd + 255) / 256, 256>>>(part, nullptr, attn, B * Hd, Hd, 4, 0);

    // 4. o = relu([x|attn] @ comb_W^T + comb_b), split-K=4
    gemm_h16<1><<<dim3(8, 2, 4), 256, GH_SMEM>>>(embedded, attn, Hd, comb_W, nullptr,
                                                 part, nullptr, nullptr,
                                                 Hd, 2 * Hd, 512, 0, 0);
    reduce_bias<<<(B * Hd + 255) / 256, 256>>>(part, comb_b, o, B * Hd, Hd, 4, 1);

    // 5. gi = o @ Wih^T ; gh = h @ Whh^T, split-K=2 each, fused gates
    gemm_h16<1><<<dim3(24, 2, 2), 256, GH_SMEM>>>(o, nullptr, Hd, gru_Wih, nullptr,
                                                  part, nullptr, nullptr,
                                                  3 * Hd, Hd, 512, 0, 0);
    gemm_h16<1><<<dim3(24, 2, 2), 256, GH_SMEM>>>(hidden, nullptr, Hd, gru_Whh, nullptr,
                                                  part + 2L * B * 3 * Hd, nullptr, nullptr,
                                                  3 * Hd, Hd, 512, 0, 0);
    gru_fuse<<<(B * Hd + 255) / 256, 256>>>(part, hidden, gru_bih, gru_bhh, out_h);

    // 6. logits = h_new @ out_W^T + out_b, lse partials fused in epilogue
    gemm_h16<1><<<dim3(NTV, 2, 1), 256, GH_SMEM>>>(out_h, nullptr, Hd, out_W, out_b,
                                                   logits, rmax, rsum,
                                                   V, Hd, Hd, 0, 1);

    // 7. lse + final subtract
    lse_reduce<<<1, 256>>>(rmax, rsum, lse);
    logp_final<<<dim3(50, B), 1024>>>(logits, lse, out_logp);
}

// round 8
// speedup vs baseline: 1.1891x; 1.1891x over previous
#include <cuda_runtime.h>
#include <cuda_fp16.h>
#include <math.h>
#include <stdint.h>

// Problem constants
#define B   256
#define Hd  1024
#define L   400
#define V   50257
#define NTV 393              // ceil(V/128)

#define OUT_H    ((long)B * V)
#define OUT_AW   ((long)B * V + (long)B * Hd)

// ---------------- scratch (device globals) ---------------------------------
__device__ float g_scores[B * L];
__device__ float g_attn[B * Hd];
__device__ float g_o[B * Hd];
__device__ float g_logits[(long)B * V];
__device__ float g_part[4L * B * 3 * Hd];     // split-K partials, sized for fused GRU [4][B][3H]
__device__ float g_rmax[(long)B * NTV];       // [row][tile] — coalesced for lse_reduce
__device__ float g_rsum[(long)B * NTV];
__device__ float g_lse[B];

// ---------------- helpers ---------------------------------------------------
__device__ __forceinline__ uint32_t smem_u32(const void* p) {
    uint32_t a;
    asm("{ .reg .u64 t; cvta.to.shared.u64 t, %1; cvt.u32.u64 %0, t; }" : "=r"(a) : "l"(p));
    return a;
}

__device__ __forceinline__ uint32_t h2bits(float x, float y) {
    __half2 h = __floats2half2_rn(x, y);
    return *(uint32_t*)&h;
}

#define SWZ128(x) ((x) ^ (((x) >> 3) & 0x70))

__device__ __forceinline__ void ldsm_x4(uint32_t* r, uint32_t addr) {
    asm volatile("ldmatrix.sync.aligned.m8n8.x4.shared.b16 {%0,%1,%2,%3}, [%4];"
                 : "=r"(r[0]), "=r"(r[1]), "=r"(r[2]), "=r"(r[3]) : "r"(addr));
}

__device__ __forceinline__ void mma_f16(float* c, const uint32_t* a, const uint32_t* b) {
    asm volatile(
        "mma.sync.aligned.m16n8k16.row.col.f32.f16.f16.f32 "
        "{%0,%1,%2,%3}, {%4,%5,%6,%7}, {%8,%9}, {%0,%1,%2,%3};"
        : "+f"(c[0]), "+f"(c[1]), "+f"(c[2]), "+f"(c[3])
        : "r"(a[0]), "r"(a[1]), "r"(a[2]), "r"(a[3]), "r"(b[0]), "r"(b[1]));
}

// fast exp (full-rate FFMA path)
__device__ __forceinline__ float fexp(float x)
{
    float t = fmaxf(x * 1.44269504f, -125.0f);
    float fi = t + 12582912.f;
    int   i = __float_as_int(fi);
    float fr = t - (fi - 12582912.f);
    float y = fr * 0.69314718f;
    float p = fmaf(y, 0.25f, 1.f);
    p = fmaf(y * p, 0.33333333f, 1.f);
    p = fmaf(y * p, 0.5f, 1.f);
    p = fmaf(y, p, 1.f);
    return __int_as_float((i + (127 - 0x4B400000)) << 23) * p;
}

// ---------------- fp16 tensor-core GEMM -------------------------------------
// C[256,N] = concat_K(A1[.,0:KA1], A2[.,KA1:K]) @ Bop (+bias)
// TRANSB=1: Bop = W[N,K]^T.  TRANSB=0: Bop = W[K,N] row-major.
// grid.y = 2 (128 rows per CTA). Split-K via blockIdx.z (chunkK).
// MODE=0: write partials at C + z*256*N (no bias).
// MODE=2: direct write with bias + fused log-softmax partials to rmax/rsum.
// Block tile 128x128x64, 256 threads, 8 warps (2m x 4n), warp tile 64x32.
#define GH_SMEM 65536

template<int TRANSB, int MODE>
__global__ __launch_bounds__(256, 1) void gemm_h16(
    const float* __restrict__ A1, const float* __restrict__ A2, int KA1,
    const float* __restrict__ W, const float* __restrict__ bias,
    float* __restrict__ C, float* __restrict__ rmax, float* __restrict__ rsum,
    int N, int K, int chunkK)
{
    extern __shared__ char smem[];
    const uint32_t sb = smem_u32(smem);

    const int t = threadIdx.x;
    const int lane = t & 31;
    const int wid = t >> 5;
    const int wm = wid >> 2;       // 0..1
    const int wn = wid & 3;        // 0..3
    const int g = lane >> 2;       // 0..7
    const int q = lane & 3;        // 0..3

    const int m0 = blockIdx.y * 128;
    const int n0 = blockIdx.x * 128;
    const int kstart = blockIdx.z * chunkK;
    const int kend = min(kstart + chunkK, K);
    const int KA2 = K - KA1;

    const int arow = t >> 4;          // 0..15 (+16*i)
    const int acol = (t & 15) * 4;    // float col 0..60

    float4 ra[8], rb[8];
    float4 rba[4], rbb[4];

    float acc[4][4][4];
    #pragma unroll
    for (int i = 0; i < 4; i++)
        #pragma unroll
        for (int j = 0; j < 4; j++)
            #pragma unroll
            for (int v = 0; v < 4; v++) acc[i][j][v] = 0.f;

    auto loadA = [&](int k0) {
        #pragma unroll
        for (int i = 0; i < 8; i++) {
            int m = m0 + arow + 16 * i;
            int k = k0 + acol;
            ra[i] = make_float4(0.f, 0.f, 0.f, 0.f);
            if (k < kend) {
                if (k < KA1) ra[i] = *(const float4*)&A1[(long)m * KA1 + k];
                else         ra[i] = *(const float4*)&A2[(long)m * KA2 + (k - KA1)];
            }
        }
    };
    auto loadB = [&](int k0) {
        if (TRANSB) {
            #pragma unroll
            for (int i = 0; i < 8; i++) {
                int n = n0 + arow + 16 * i;
                int k = k0 + acol;
                rb[i] = make_float4(0.f, 0.f, 0.f, 0.f);
                if (n < N && k < kend) rb[i] = *(const float4*)&W[(long)n * K + k];
            }
        } else {
            #pragma unroll
            for (int i = 0; i < 4; i++) {
                int cell = t + i * 256;
                int kp = cell >> 5;         // 0..31
                int nq = cell & 31;         // 0..31
                int k = k0 + 2 * kp;
                int n = n0 + nq * 4;
                rba[i] = make_float4(0.f, 0.f, 0.f, 0.f);
                rbb[i] = make_float4(0.f, 0.f, 0.f, 0.f);
                if (k < kend && n < N) {
                    rba[i] = *(const float4*)&W[(long)k * N + n];
                    if (k + 1 < kend) rbb[i] = *(const float4*)&W[(long)(k + 1) * N + n];
                }
            }
        }
    };
    auto storeAB = [&](int s) {
        char* Ab = smem + s * 32768;
        char* Bb = smem + s * 32768 + 16384;
        #pragma unroll
        for (int i = 0; i < 8; i++) {
            int row = arow + 16 * i;
            uint32_t off = SWZ128((uint32_t)(row * 128 + acol * 2));
            *(uint2*)(Ab + off) = make_uint2(h2bits(ra[i].x, ra[i].y), h2bits(ra[i].z, ra[i].w));
        }
        if (TRANSB) {
            #pragma unroll
            for (int i = 0; i < 8; i++) {
                int row = arow + 16 * i;
                uint32_t off = SWZ128((uint32_t)(row * 128 + acol * 2));
                *(uint2*)(Bb + off) = make_uint2(h2bits(rb[i].x, rb[i].y), h2bits(rb[i].z, rb[i].w));
            }
        } else {
            #pragma unroll
            for (int i = 0; i < 4; i++) {
                int cell = t + i * 256;
                int kp = cell >> 5;
                int nq = cell & 31;
                const float* fa = (const float*)&rba[i];
                const float* fb = (const float*)&rbb[i];
                #pragma unroll
                for (int j = 0; j < 4; j++) {
                    int row = nq * 4 + j;
                    uint32_t off = SWZ128((uint32_t)(row * 128 + kp * 4));
                    *(uint32_t*)(Bb + off) = h2bits(fa[j], fb[j]);
                }
            }
        }
    };

    const int a_row = lane & 15;
    const int a_cb = (lane >> 4) << 4;
    const int b_row = (lane & 7) + ((lane >> 4) << 3);
    const int b_cb = ((lane >> 3) & 1) << 4;

    auto compute = [&](int s) {
        const uint32_t Ab = sb + s * 32768;
        const uint32_t Bb = Ab + 16384;
        #pragma unroll
        for (int ks = 0; ks < 4; ks++) {
            uint32_t af[4][4], bf[2][4];
            #pragma unroll
            for (int mt = 0; mt < 4; mt++) {
                int r = wm * 64 + mt * 16 + a_row;
                ldsm_x4(af[mt], Ab + SWZ128((uint32_t)(r * 128 + ks * 32 + a_cb)));
            }
            #pragma unroll
            for (int np = 0; np < 2; np++) {
                int r = wn * 32 + np * 16 + b_row;
                ldsm_x4(bf[np], Bb + SWZ128((uint32_t)(r * 128 + ks * 32 + b_cb)));
            }
            #pragma unroll
            for (int mt = 0; mt < 4; mt++)
                #pragma unroll
                for (int nt = 0; nt < 4; nt++)
                    mma_f16(acc[mt][nt], af[mt], &bf[nt >> 1][(nt & 1) * 2]);
        }
    };

    const int ntiles = (kend - kstart + 63) / 64;

    loadA(kstart); loadB(kstart);
    storeAB(0);
    __syncthreads();
    for (int c = 1; c < ntiles; c++) {
        loadA(kstart + c * 64); loadB(kstart + c * 64);
        compute((c - 1) & 1);
        __syncthreads();
        storeAB(c & 1);
        __syncthreads();
    }
    compute((ntiles - 1) & 1);

    // ---- epilogue ----
    if constexpr (MODE == 0) {
        float* Cw = C + (long)blockIdx.z * 256 * N;
        #pragma unroll
        for (int mt = 0; mt < 4; mt++) {
            int row = m0 + wm * 64 + mt * 16 + g;
            #pragma unroll
            for (int nt = 0; nt < 4; nt++) {
                int col = n0 + wn * 32 + nt * 8 + 2 * q;
                if (col < N)     Cw[(long)row * N + col]           = acc[mt][nt][0];
                if (col + 1 < N) Cw[(long)row * N + col + 1]       = acc[mt][nt][1];
                if (col < N)     Cw[(long)(row + 8) * N + col]     = acc[mt][nt][2];
                if (col + 1 < N) Cw[(long)(row + 8) * N + col + 1] = acc[mt][nt][3];
            }
        }
    } else {
        // direct + bias, write C, and emit per-tile row (max, expsum)
        #pragma unroll
        for (int mt = 0; mt < 4; mt++) {
            int row = m0 + wm * 64 + mt * 16 + g;
            #pragma unroll
            for (int nt = 0; nt < 4; nt++) {
                int col = n0 + wn * 32 + nt * 8 + 2 * q;
                float b0 = (col < N) ? bias[col] : 0.f;
                float b1 = (col + 1 < N) ? bias[col + 1] : 0.f;
                acc[mt][nt][0] += b0; acc[mt][nt][1] += b1;
                acc[mt][nt][2] += b0; acc[mt][nt][3] += b1;
                if (col < N)     C[(long)row * N + col]           = acc[mt][nt][0];
                if (col + 1 < N) C[(long)row * N + col + 1]       = acc[mt][nt][1];
                if (col < N)     C[(long)(row + 8) * N + col]     = acc[mt][nt][2];
                if (col + 1 < N) C[(long)(row + 8) * N + col + 1] = acc[mt][nt][3];
            }
        }
        float* redm = (float*)smem;          // [4][128]
        float* reds = redm + 512;
        __syncthreads();                     // stages dead now
        #pragma unroll
        for (int mt = 0; mt < 4; mt++) {
            #pragma unroll
            for (int half = 0; half < 2; half++) {
                float mv = -1e30f;
                #pragma unroll
                for (int nt = 0; nt < 4; nt++) {
                    #pragma unroll
                    for (int k2 = 0; k2 < 2; k2++) {
                        int col = n0 + wn * 32 + nt * 8 + 2 * q + k2;
                        float v = (col < N) ? acc[mt][nt][half * 2 + k2] : -1e30f;
                        mv = fmaxf(mv, v);
                    }
                }
                float sv = 0.f;
                #pragma unroll
                for (int nt = 0; nt < 4; nt++) {
                    #pragma unroll
                    for (int k2 = 0; k2 < 2; k2++) {
                        int col = n0 + wn * 32 + nt * 8 + 2 * q + k2;
                        float v = (col < N) ? acc[mt][nt][half * 2 + k2] : -1e30f;
                        sv += fexp(v - mv);
                    }
                }
                #pragma unroll
                for (int off = 1; off <= 2; off <<= 1) {
                    float mo = __shfl_xor_sync(0xffffffff, mv, off);
                    float so = __shfl_xor_sync(0xffffffff, sv, off);
                    float mn = fmaxf(mv, mo);
                    sv = sv * fexp(mv - mn) + so * fexp(mo - mn);
                    mv = mn;
                }
                if (q == 0) {
                    int rloc = wm * 64 + mt * 16 + g + half * 8;   // 0..127
                    redm[wn * 128 + rloc] = mv;
                    reds[wn * 128 + rloc] = sv;
                }
            }
        }
        __syncthreads();
        if (t < 128) {
            float m = -1e30f, s = 0.f;
            #pragma unroll
            for (int w = 0; w < 4; w++) {
                float mw = redm[w * 128 + t], sw = reds[w * 128 + t];
                float mn = fmaxf(m, mw);
                s = s * fexp(m - mn) + sw * fexp(mw - mn);
                m = mn;
            }
            // layout [row][tile] for coalesced lse_reduce
            rmax[(long)(m0 + t) * NTV + blockIdx.x] = m;
            rsum[(long)(m0 + t) * NTV + blockIdx.x] = s;
        }
    }
}

// ---------------- split-K reduce (+bias, +relu) — deterministic -------------
__global__ void reduce_bias(const float* __restrict__ part, const float* __restrict__ bias,
                            float* __restrict__ out, int MN, int N, int SK, int relu)
{
    int idx = blockIdx.x * blockDim.x + threadIdx.x;
    if (idx >= MN) return;
    float s = 0.f;
    for (int c = 0; c < SK; c++) s += part[(long)c * MN + idx];
    if (bias) s += bias[idx % N];
    if (relu) s = fmaxf(s, 0.f);
    out[idx] = s;
}

// ---------------- fused GRU: split-K reduce of gi/gh + gates ----------------
__global__ void gru_fuse(const float* __restrict__ part, const float* __restrict__ hidden,
                         const float* __restrict__ bih, const float* __restrict__ bhh,
                         float* __restrict__ h_new)
{
    int idx = blockIdx.x * blockDim.x + threadIdx.x;
    if (idx >= B * Hd) return;
    int b = idx / Hd, j = idx - b * Hd;
    const long NN = 3 * Hd;
    const long MN = (long)B * NN;
    const float* giA = part;            // [2][B][3H]
    const float* ghA = part + 2 * MN;   // [2][B][3H]
    long base = (long)b * NN + j;

    float ir = giA[base] + giA[MN + base] + bih[j];
    float iz = giA[base + Hd] + giA[MN + base + Hd] + bih[j + Hd];
    float in_ = giA[base + 2 * Hd] + giA[MN + base + 2 * Hd] + bih[j + 2 * Hd];
    float hr = ghA[base] + ghA[MN + base] + bhh[j];
    float hz = ghA[base + Hd] + ghA[MN + base + Hd] + bhh[j + Hd];
    float hn = ghA[base + 2 * Hd] + ghA[MN + base + 2 * Hd] + bhh[j + 2 * Hd];

    float r = 1.f / (1.f + expf(-(ir + hr)));
    float z = 1.f / (1.f + expf(-(iz + hz)));
    float nn = tanhf(in_ + r * hn);
    h_new[idx] = (1.f - z) * nn + z * hidden[idx];
}

// ---------------- warp-per-row softmax (L=400) -------------------------------
__global__ void softmax_warp(const float* __restrict__ in, float* __restrict__ out, int n)
{
    int w = (blockIdx.x * blockDim.x + threadIdx.x) >> 5;
    int lid = threadIdx.x & 31;
    if (w >= B) return;
    const float* x = in + (long)w * n;
    float* y = out + (long)w * n;

    float m = -1e30f;
    for (int i = lid; i < n; i += 32) m = fmaxf(m, x[i]);
    #pragma unroll
    for (int o = 16; o > 0; o >>= 1) m = fmaxf(m, __shfl_xor_sync(0xffffffff, m, o));
    float s = 0.f;
    for (int i = lid; i < n; i += 32) s += fexp(x[i] - m);
    #pragma unroll
    for (int o = 16; o > 0; o >>= 1) s += __shfl_xor_sync(0xffffffff, s, o);
    float inv = 1.f / s;
    for (int i = lid; i < n; i += 32) y[i] = fexp(x[i] - m) * inv;
}

// ---------------- parallel lse reduce: one block per row ---------------------
__global__ void lse_reduce(const float* __restrict__ rmax, const float* __restrict__ rsum,
                           float* __restrict__ lse)
{
    int row = blockIdx.x;
    int t = threadIdx.x;   // 128
    float m = -1e30f, s = 0.f;
    for (int tile = t; tile < NTV; tile += 128) {
        float mw = rmax[(long)row * NTV + tile];
        float sw = rsum[(long)row * NTV + tile];
        float mn = fmaxf(m, mw);
        s = s * fexp(m - mn) + sw * fexp(mw - mn);
        m = mn;
    }
    #pragma unroll
    for (int o = 16; o > 0; o >>= 1) {
        float mo = __shfl_xor_sync(0xffffffff, m, o);
        float so = __shfl_xor_sync(0xffffffff, s, o);
        float mn = fmaxf(m, mo);
        s = s * fexp(m - mn) + so * fexp(mo - mn);
        m = mn;
    }
    __shared__ float sm[4], ss[4];
    if ((t & 31) == 0) { sm[t >> 5] = m; ss[t >> 5] = s; }
    __syncthreads();
    if (t == 0) {
        float M = sm[0], S = ss[0];
        #pragma unroll
        for (int w = 1; w < 4; w++) {
            float mn = fmaxf(M, sm[w]);
            S = S * fexp(M - mn) + ss[w] * fexp(sm[w] - mn);
            M = mn;
        }
        lse[row] = M + logf(S);
    }
}

// ---------------- final: logp = logits - lse ---------------------------------
__global__ void logp_final(const float* __restrict__ logits, const float* __restrict__ lse,
                           float* __restrict__ out)
{
    int col = blockIdx.x * 1024 + threadIdx.x;
    int row = blockIdx.y;
    if (col < V) {
        long i = (long)row * V + col;
        out[i] = logits[i] - lse[row];
    }
}

// ---------------- launch -----------------------------------------------------
extern "C" void kernel_launch(void* const* d_in, const int* in_sizes, int n_in,
                              void* d_out, int out_size)
{
    const float* embedded = (const float*)d_in[0];
    const float* hidden   = (const float*)d_in[1];
    const float* enc      = (const float*)d_in[2];
    const float* attn_W   = (const float*)d_in[3];
    const float* attn_b   = (const float*)d_in[4];
    const float* comb_W   = (const float*)d_in[5];
    const float* comb_b   = (const float*)d_in[6];
    const float* gru_Wih  = (const float*)d_in[7];
    const float* gru_Whh  = (const float*)d_in[8];
    const float* gru_bih  = (const float*)d_in[9];
    const float* gru_bhh  = (const float*)d_in[10];
    const float* out_W    = (const float*)d_in[11];
    const float* out_b    = (const float*)d_in[12];

    float* out = (float*)d_out;
    float* out_logp = out;
    float* out_h    = out + OUT_H;
    float* out_aw   = out + OUT_AW;

    float *scores, *attn, *o, *logits, *part, *rmax, *rsum, *lse;
    cudaGetSymbolAddress((void**)&scores, g_scores);
    cudaGetSymbolAddress((void**)&attn, g_attn);
    cudaGetSymbolAddress((void**)&o, g_o);
    cudaGetSymbolAddress((void**)&logits, g_logits);
    cudaGetSymbolAddress((void**)&part, g_part);
    cudaGetSymbolAddress((void**)&rmax, g_rmax);
    cudaGetSymbolAddress((void**)&rsum, g_rsum);
    cudaGetSymbolAddress((void**)&lse, g_lse);

    cudaFuncSetAttribute((const void*)gemm_h16<1, 0>, cudaFuncAttributeMaxDynamicSharedMemorySize, GH_SMEM);
    cudaFuncSetAttribute((const void*)gemm_h16<0, 0>, cudaFuncAttributeMaxDynamicSharedMemorySize, GH_SMEM);
    cudaFuncSetAttribute((const void*)gemm_h16<1, 2>, cudaFuncAttributeMaxDynamicSharedMemorySize, GH_SMEM);

    // 1. scores = [x|h] @ attn_W^T (+attn_b), split-K=8
    gemm_h16<1, 0><<<dim3(4, 2, 8), 256, GH_SMEM>>>(embedded, hidden, Hd, attn_W, nullptr,
                                                    part, nullptr, nullptr, L, 2 * Hd, 256);
    reduce_bias<<<(B * L + 255) / 256, 256>>>(part, attn_b, scores, B * L, L, 8, 0);

    // 2. attn_weights = softmax(scores) -> out_aw
    softmax_warp<<<32, 256>>>(scores, out_aw, L);

    // 3. attn_applied = attn_weights @ enc (NN), split-K=4
    gemm_h16<0, 0><<<dim3(8, 2, 4), 256, GH_SMEM>>>(out_aw, nullptr, L, enc, nullptr,
                                                    part, nullptr, nullptr, Hd, L, 128);
    reduce_bias<<<(B * Hd + 255) / 256, 256>>>(part, nullptr, attn, B * Hd, Hd, 4, 0);

    // 4. o = relu([x|attn] @ comb_W^T + comb_b), split-K=4
    gemm_h16<1, 0><<<dim3(8, 2, 4), 256, GH_SMEM>>>(embedded, attn, Hd, comb_W, nullptr,
                                                    part, nullptr, nullptr, Hd, 2 * Hd, 512);
    reduce_bias<<<(B * Hd + 255) / 256, 256>>>(part, comb_b, o, B * Hd, Hd, 4, 1);

    // 5. gi = o @ Wih^T ; gh = h @ Whh^T, split-K=2 each, fused gates
    gemm_h16<1, 0><<<dim3(24, 2, 2), 256, GH_SMEM>>>(o, nullptr, Hd, gru_Wih, nullptr,
                                                     part, nullptr, nullptr, 3 * Hd, Hd, 512);
    gemm_h16<1, 0><<<dim3(24, 2, 2), 256, GH_SMEM>>>(hidden, nullptr, Hd, gru_Whh, nullptr,
                                                     part + 2L * B * 3 * Hd, nullptr, nullptr,
                                                     3 * Hd, Hd, 512);
    gru_fuse<<<(B * Hd + 255) / 256, 256>>>(part, hidden, gru_bih, gru_bhh, out_h);

    // 6. logits = h_new @ out_W^T + out_b, lse partials fused in epilogue
    gemm_h16<1, 2><<<dim3(NTV, 2, 1), 256, GH_SMEM>>>(out_h, nullptr, Hd, out_W, out_b,
                                                      logits, rmax, rsum, V, Hd, Hd);

    // 7. lse (parallel: block per row) + final subtract
    lse_reduce<<<B, 128>>>(rmax, rsum, lse);
    logp_final<<<dim3(50, B), 1024>>>(logits, lse, out_logp);
}

// round 9
// speedup vs baseline: 1.5401x; 1.2952x over previous
#include <cuda_runtime.h>
#include <cuda_fp16.h>
#include <math.h>
#include <stdint.h>

// Problem constants
#define B   256
#define Hd  1024
#define L   400
#define V   50257
#define NTV 393              // ceil(V/128)

#define OUT_H    ((long)B * V)
#define OUT_AW   ((long)B * V + (long)B * Hd)

// ---------------- scratch (device globals) ---------------------------------
__device__ float g_scores[B * L];
__device__ float g_attn[B * Hd];
__device__ float g_o[B * Hd];
__device__ float g_part[4L * B * 3 * Hd];     // split-K partials, sized for fused GRU [4][B][3H]
__device__ float g_rsum[(long)B * NTV];       // [row][tile] exp-sums
__device__ float g_lse[B];

// ---------------- helpers ---------------------------------------------------
__device__ __forceinline__ uint32_t smem_u32(const void* p) {
    uint32_t a;
    asm("{ .reg .u64 t; cvta.to.shared.u64 t, %1; cvt.u32.u64 %0, t; }" : "=r"(a) : "l"(p));
    return a;
}

__device__ __forceinline__ uint32_t h2bits(float x, float y) {
    __half2 h = __floats2half2_rn(x, y);
    return *(uint32_t*)&h;
}

#define SWZ128(x) ((x) ^ (((x) >> 3) & 0x70))

__device__ __forceinline__ void ldsm_x4(uint32_t* r, uint32_t addr) {
    asm volatile("ldmatrix.sync.aligned.m8n8.x4.shared.b16 {%0,%1,%2,%3}, [%4];"
                 : "=r"(r[0]), "=r"(r[1]), "=r"(r[2]), "=r"(r[3]) : "r"(addr));
}

__device__ __forceinline__ void mma_f16(float* c, const uint32_t* a, const uint32_t* b) {
    asm volatile(
        "mma.sync.aligned.m16n8k16.row.col.f32.f16.f16.f32 "
        "{%0,%1,%2,%3}, {%4,%5,%6,%7}, {%8,%9}, {%0,%1,%2,%3};"
        : "+f"(c[0]), "+f"(c[1]), "+f"(c[2]), "+f"(c[3])
        : "r"(a[0]), "r"(a[1]), "r"(a[2]), "r"(a[3]), "r"(b[0]), "r"(b[1]));
}

// fast exp (full-rate FFMA path)
__device__ __forceinline__ float fexp(float x)
{
    float t = fmaxf(x * 1.44269504f, -125.0f);
    float fi = t + 12582912.f;
    int   i = __float_as_int(fi);
    float fr = t - (fi - 12582912.f);
    float y = fr * 0.69314718f;
    float p = fmaf(y, 0.25f, 1.f);
    p = fmaf(y * p, 0.33333333f, 1.f);
    p = fmaf(y * p, 0.5f, 1.f);
    p = fmaf(y, p, 1.f);
    return __int_as_float((i + (127 - 0x4B400000)) << 23) * p;
}

// ---------------- fp16 tensor-core GEMM -------------------------------------
// C[256,N] = A @ Bop (+bias).  CONCAT=1: A = concat_K(A1[.,0:KA1], A2[.,KA1:K]).
// TRANSB=1: Bop = W[N,K]^T.  TRANSB=0: Bop = W[K,N] row-major.
// grid.y = 2 (128 rows per CTA). Split-K via blockIdx.z (chunkK).
// MODE=0: write partials at C + z*256*N (no bias).
// MODE=2: direct write with bias + per-tile row exp-sums (no max — bounded logits).
// Block tile 128x128x64, 256 threads, 8 warps (2m x 4n), warp tile 64x32.
#define GH_SMEM 65536

template<int TRANSB, int CONCAT, int MODE>
__global__ __launch_bounds__(256, 1) void gemm_h16(
    const float* __restrict__ A1, const float* __restrict__ A2, int KA1,
    const float* __restrict__ W, const float* __restrict__ bias,
    float* __restrict__ C, float* __restrict__ rsum,
    int N, int K, int chunkK)
{
    extern __shared__ char smem[];
    const uint32_t sb = smem_u32(smem);

    const int t = threadIdx.x;
    const int lane = t & 31;
    const int wid = t >> 5;
    const int wm = wid >> 2;       // 0..1
    const int wn = wid & 3;        // 0..3
    const int g = lane >> 2;       // 0..7
    const int q = lane & 3;        // 0..3

    const int m0 = blockIdx.y * 128;
    const int n0 = blockIdx.x * 128;
    const int kstart = blockIdx.z * chunkK;
    const int kend = min(kstart + chunkK, K);
    const int KA2 = K - KA1;

    const int arow = t >> 4;          // 0..15 (+16*i)
    const int acol = (t & 15) * 4;    // float col 0..60

    float4 ra[8], rb[8];
    float4 rba[4], rbb[4];

    float acc[4][4][4];
    #pragma unroll
    for (int i = 0; i < 4; i++)
        #pragma unroll
        for (int j = 0; j < 4; j++)
            #pragma unroll
            for (int v = 0; v < 4; v++) acc[i][j][v] = 0.f;

    auto loadA = [&](int k0) {
        #pragma unroll
        for (int i = 0; i < 8; i++) {
            int m = m0 + arow + 16 * i;
            int k = k0 + acol;
            ra[i] = make_float4(0.f, 0.f, 0.f, 0.f);
            if (k < kend) {
                if constexpr (CONCAT) {
                    if (k < KA1) ra[i] = *(const float4*)&A1[(long)m * KA1 + k];
                    else         ra[i] = *(const float4*)&A2[(long)m * KA2 + (k - KA1)];
                } else {
                    ra[i] = *(const float4*)&A1[(long)m * K + k];
                }
            }
        }
    };
    auto loadB = [&](int k0) {
        if (TRANSB) {
            #pragma unroll
            for (int i = 0; i < 8; i++) {
                int n = n0 + arow + 16 * i;
                int k = k0 + acol;
                rb[i] = make_float4(0.f, 0.f, 0.f, 0.f);
                if (n < N && k < kend) rb[i] = *(const float4*)&W[(long)n * K + k];
            }
        } else {
            #pragma unroll
            for (int i = 0; i < 4; i++) {
                int cell = t + i * 256;
                int kp = cell >> 5;         // 0..31
                int nq = cell & 31;         // 0..31
                int k = k0 + 2 * kp;
                int n = n0 + nq * 4;
                rba[i] = make_float4(0.f, 0.f, 0.f, 0.f);
                rbb[i] = make_float4(0.f, 0.f, 0.f, 0.f);
                if (k < kend && n < N) {
                    rba[i] = *(const float4*)&W[(long)k * N + n];
                    if (k + 1 < kend) rbb[i] = *(const float4*)&W[(long)(k + 1) * N + n];
                }
            }
        }
    };
    auto storeAB = [&](int s) {
        char* Ab = smem + s * 32768;
        char* Bb = smem + s * 32768 + 16384;
        #pragma unroll
        for (int i = 0; i < 8; i++) {
            int row = arow + 16 * i;
            uint32_t off = SWZ128((uint32_t)(row * 128 + acol * 2));
            *(uint2*)(Ab + off) = make_uint2(h2bits(ra[i].x, ra[i].y), h2bits(ra[i].z, ra[i].w));
        }
        if (TRANSB) {
            #pragma unroll
            for (int i = 0; i < 8; i++) {
                int row = arow + 16 * i;
                uint32_t off = SWZ128((uint32_t)(row * 128 + acol * 2));
                *(uint2*)(Bb + off) = make_uint2(h2bits(rb[i].x, rb[i].y), h2bits(rb[i].z, rb[i].w));
            }
        } else {
            #pragma unroll
            for (int i = 0; i < 4; i++) {
                int cell = t + i * 256;
                int kp = cell >> 5;
                int nq = cell & 31;
                const float* fa = (const float*)&rba[i];
                const float* fb = (const float*)&rbb[i];
                #pragma unroll
                for (int j = 0; j < 4; j++) {
                    int row = nq * 4 + j;
                    uint32_t off = SWZ128((uint32_t)(row * 128 + kp * 4));
                    *(uint32_t*)(Bb + off) = h2bits(fa[j], fb[j]);
                }
            }
        }
    };

    const int a_row = lane & 15;
    const int a_cb = (lane >> 4) << 4;
    const int b_row = (lane & 7) + ((lane >> 4) << 3);
    const int b_cb = ((lane >> 3) & 1) << 4;

    auto compute = [&](int s) {
        const uint32_t Ab = sb + s * 32768;
        const uint32_t Bb = Ab + 16384;
        #pragma unroll
        for (int ks = 0; ks < 4; ks++) {
            uint32_t af[4][4], bf[2][4];
            #pragma unroll
            for (int mt = 0; mt < 4; mt++) {
                int r = wm * 64 + mt * 16 + a_row;
                ldsm_x4(af[mt], Ab + SWZ128((uint32_t)(r * 128 + ks * 32 + a_cb)));
            }
            #pragma unroll
            for (int np = 0; np < 2; np++) {
                int r = wn * 32 + np * 16 + b_row;
                ldsm_x4(bf[np], Bb + SWZ128((uint32_t)(r * 128 + ks * 32 + b_cb)));
            }
            #pragma unroll
            for (int mt = 0; mt < 4; mt++)
                #pragma unroll
                for (int nt = 0; nt < 4; nt++)
                    mma_f16(acc[mt][nt], af[mt], &bf[nt >> 1][(nt & 1) * 2]);
        }
    };

    const int ntiles = (kend - kstart + 63) / 64;

    // single-sync double buffer: compute(c-1) reads buf (c-1)&1 while store(c)
    // fills buf c&1; one barrier per chunk orders both hazards.
    loadA(kstart); loadB(kstart);
    storeAB(0);
    __syncthreads();
    for (int c = 1; c < ntiles; c++) {
        loadA(kstart + c * 64); loadB(kstart + c * 64);
        compute((c - 1) & 1);
        storeAB(c & 1);
        __syncthreads();
    }
    compute((ntiles - 1) & 1);

    // ---- epilogue ----
    if constexpr (MODE == 0) {
        float* Cw = C + (long)blockIdx.z * 256 * N;
        #pragma unroll
        for (int mt = 0; mt < 4; mt++) {
            int row = m0 + wm * 64 + mt * 16 + g;
            #pragma unroll
            for (int nt = 0; nt < 4; nt++) {
                int col = n0 + wn * 32 + nt * 8 + 2 * q;
                if (col < N)     Cw[(long)row * N + col]           = acc[mt][nt][0];
                if (col + 1 < N) Cw[(long)row * N + col + 1]       = acc[mt][nt][1];
                if (col < N)     Cw[(long)(row + 8) * N + col]     = acc[mt][nt][2];
                if (col + 1 < N) Cw[(long)(row + 8) * N + col + 1] = acc[mt][nt][3];
            }
        }
    } else {
        // direct + bias + store + bare exp-sum (logits bounded; no max needed)
        float se[4][2];
        #pragma unroll
        for (int mt = 0; mt < 4; mt++) { se[mt][0] = 0.f; se[mt][1] = 0.f; }
        #pragma unroll
        for (int mt = 0; mt < 4; mt++) {
            int row = m0 + wm * 64 + mt * 16 + g;
            #pragma unroll
            for (int nt = 0; nt < 4; nt++) {
                int col = n0 + wn * 32 + nt * 8 + 2 * q;
                float b0 = (col < N) ? bias[col] : 0.f;
                float b1 = (col + 1 < N) ? bias[col + 1] : 0.f;
                float v0 = acc[mt][nt][0] + b0, v1 = acc[mt][nt][1] + b1;
                float v2 = acc[mt][nt][2] + b0, v3 = acc[mt][nt][3] + b1;
                if (col < N)     { C[(long)row * N + col]           = v0; se[mt][0] += fexp(v0); }
                if (col + 1 < N) { C[(long)row * N + col + 1]       = v1; se[mt][0] += fexp(v1); }
                if (col < N)     { C[(long)(row + 8) * N + col]     = v2; se[mt][1] += fexp(v2); }
                if (col + 1 < N) { C[(long)(row + 8) * N + col + 1] = v3; se[mt][1] += fexp(v3); }
            }
        }
        float* reds = (float*)smem;          // [4][128]
        __syncthreads();                     // stages dead now
        #pragma unroll
        for (int mt = 0; mt < 4; mt++) {
            #pragma unroll
            for (int half = 0; half < 2; half++) {
                float sv = se[mt][half];
                sv += __shfl_xor_sync(0xffffffff, sv, 1);
                sv += __shfl_xor_sync(0xffffffff, sv, 2);
                if (q == 0) {
                    int rloc = wm * 64 + mt * 16 + g + half * 8;   // 0..127
                    reds[wn * 128 + rloc] = sv;
                }
            }
        }
        __syncthreads();
        if (t < 128) {
            float s = reds[t] + reds[128 + t] + reds[256 + t] + reds[384 + t];
            rsum[(long)(m0 + t) * NTV + blockIdx.x] = s;   // [row][tile]
        }
    }
}

// ---------------- split-K reduce (+bias, +relu) — deterministic -------------
__global__ void reduce_bias(const float* __restrict__ part, const float* __restrict__ bias,
                            float* __restrict__ out, int MN, int N, int SK, int relu)
{
    int idx = blockIdx.x * blockDim.x + threadIdx.x;
    if (idx >= MN) return;
    float s = 0.f;
    for (int c = 0; c < SK; c++) s += part[(long)c * MN + idx];
    if (bias) s += bias[idx % N];
    if (relu) s = fmaxf(s, 0.f);
    out[idx] = s;
}

// ---------------- fused GRU: split-K reduce of gi/gh + gates ----------------
__global__ void gru_fuse(const float* __restrict__ part, const float* __restrict__ hidden,
                         const float* __restrict__ bih, const float* __restrict__ bhh,
                         float* __restrict__ h_new)
{
    int idx = blockIdx.x * blockDim.x + threadIdx.x;
    if (idx >= B * Hd) return;
    int b = idx / Hd, j = idx - b * Hd;
    const long NN = 3 * Hd;
    const long MN = (long)B * NN;
    const float* giA = part;            // [2][B][3H]
    const float* ghA = part + 2 * MN;   // [2][B][3H]
    long base = (long)b * NN + j;

    float ir = giA[base] + giA[MN + base] + bih[j];
    float iz = giA[base + Hd] + giA[MN + base + Hd] + bih[j + Hd];
    float in_ = giA[base + 2 * Hd] + giA[MN + base + 2 * Hd] + bih[j + 2 * Hd];
    float hr = ghA[base] + ghA[MN + base] + bhh[j];
    float hz = ghA[base + Hd] + ghA[MN + base + Hd] + bhh[j + Hd];
    float hn = ghA[base + 2 * Hd] + ghA[MN + base + 2 * Hd] + bhh[j + 2 * Hd];

    float r = 1.f / (1.f + expf(-(ir + hr)));
    float z = 1.f / (1.f + expf(-(iz + hz)));
    float nn = tanhf(in_ + r * hn);
    h_new[idx] = (1.f - z) * nn + z * hidden[idx];
}

// ---------------- warp-per-row softmax (L=400) -------------------------------
__global__ void softmax_warp(const float* __restrict__ in, float* __restrict__ out, int n)
{
    int w = (blockIdx.x * blockDim.x + threadIdx.x) >> 5;
    int lid = threadIdx.x & 31;
    if (w >= B) return;
    const float* x = in + (long)w * n;
    float* y = out + (long)w * n;

    float m = -1e30f;
    for (int i = lid; i < n; i += 32) m = fmaxf(m, x[i]);
    #pragma unroll
    for (int o = 16; o > 0; o >>= 1) m = fmaxf(m, __shfl_xor_sync(0xffffffff, m, o));
    float s = 0.f;
    for (int i = lid; i < n; i += 32) s += fexp(x[i] - m);
    #pragma unroll
    for (int o = 16; o > 0; o >>= 1) s += __shfl_xor_sync(0xffffffff, s, o);
    float inv = 1.f / s;
    for (int i = lid; i < n; i += 32) y[i] = fexp(x[i] - m) * inv;
}

// ---------------- parallel lse: one block per row, plain sum -----------------
__global__ void lse_reduce(const float* __restrict__ rsum, float* __restrict__ lse)
{
    int row = blockIdx.x;
    int t = threadIdx.x;   // 128
    float s = 0.f;
    for (int tile = t; tile < NTV; tile += 128) s += rsum[(long)row * NTV + tile];
    #pragma unroll
    for (int o = 16; o > 0; o >>= 1) s += __shfl_xor_sync(0xffffffff, s, o);
    __shared__ float ss[4];
    if ((t & 31) == 0) ss[t >> 5] = s;
    __syncthreads();
    if (t == 0) lse[row] = logf(ss[0] + ss[1] + ss[2] + ss[3]);
}

// ---------------- final: logp -= lse (in place) ------------------------------
__global__ void logp_sub(float* __restrict__ logp, const float* __restrict__ lse)
{
    int col = blockIdx.x * 1024 + threadIdx.x;
    int row = blockIdx.y;
    if (col < V) logp[(long)row * V + col] -= lse[row];
}

// ---------------- launch -----------------------------------------------------
extern "C" void kernel_launch(void* const* d_in, const int* in_sizes, int n_in,
                              void* d_out, int out_size)
{
    const float* embedded = (const float*)d_in[0];
    const float* hidden   = (const float*)d_in[1];
    const float* enc      = (const float*)d_in[2];
    const float* attn_W   = (const float*)d_in[3];
    const float* attn_b   = (const float*)d_in[4];
    const float* comb_W   = (const float*)d_in[5];
    const float* comb_b   = (const float*)d_in[6];
    const float* gru_Wih  = (const float*)d_in[7];
    const float* gru_Whh  = (const float*)d_in[8];
    const float* gru_bih  = (const float*)d_in[9];
    const float* gru_bhh  = (const float*)d_in[10];
    const float* out_W    = (const float*)d_in[11];
    const float* out_b    = (const float*)d_in[12];

    float* out = (float*)d_out;
    float* out_logp = out;
    float* out_h    = out + OUT_H;
    float* out_aw   = out + OUT_AW;

    float *scores, *attn, *o, *part, *rsum, *lse;
    cudaGetSymbolAddress((void**)&scores, g_scores);
    cudaGetSymbolAddress((void**)&attn, g_attn);
    cudaGetSymbolAddress((void**)&o, g_o);
    cudaGetSymbolAddress((void**)&part, g_part);
    cudaGetSymbolAddress((void**)&rsum, g_rsum);
    cudaGetSymbolAddress((void**)&lse, g_lse);

    cudaFuncSetAttribute((const void*)gemm_h16<1, 1, 0>, cudaFuncAttributeMaxDynamicSharedMemorySize, GH_SMEM);
    cudaFuncSetAttribute((const void*)gemm_h16<1, 0, 0>, cudaFuncAttributeMaxDynamicSharedMemorySize, GH_SMEM);
    cudaFuncSetAttribute((const void*)gemm_h16<0, 0, 0>, cudaFuncAttributeMaxDynamicSharedMemorySize, GH_SMEM);
    cudaFuncSetAttribute((const void*)gemm_h16<1, 0, 2>, cudaFuncAttributeMaxDynamicSharedMemorySize, GH_SMEM);

    // 1. scores = [x|h] @ attn_W^T (+attn_b), split-K=8
    gemm_h16<1, 1, 0><<<dim3(4, 2, 8), 256, GH_SMEM>>>(embedded, hidden, Hd, attn_W, nullptr,
                                                       part, nullptr, L, 2 * Hd, 256);
    reduce_bias<<<(B * L + 255) / 256, 256>>>(part, attn_b, scores, B * L, L, 8, 0);

    // 2. attn_weights = softmax(scores) -> out_aw
    softmax_warp<<<32, 256>>>(scores, out_aw, L);

    // 3. attn_applied = attn_weights @ enc (NN), split-K=4
    gemm_h16<0, 0, 0><<<dim3(8, 2, 4), 256, GH_SMEM>>>(out_aw, nullptr, L, enc, nullptr,
                                                       part, nullptr, Hd, L, 128);
    reduce_bias<<<(B * Hd + 255) / 256, 256>>>(part, nullptr, attn, B * Hd, Hd, 4, 0);

    // 4. o = relu([x|attn] @ comb_W^T + comb_b), split-K=4
    gemm_h16<1, 1, 0><<<dim3(8, 2, 4), 256, GH_SMEM>>>(embedded, attn, Hd, comb_W, nullptr,
                                                       part, nullptr, Hd, 2 * Hd, 512);
    reduce_bias<<<(B * Hd + 255) / 256, 256>>>(part, comb_b, o, B * Hd, Hd, 4, 1);

    // 5. gi = o @ Wih^T ; gh = h @ Whh^T, split-K=2 each, fused gates
    gemm_h16<1, 0, 0><<<dim3(24, 2, 2), 256, GH_SMEM>>>(o, nullptr, Hd, gru_Wih, nullptr,
                                                        part, nullptr, 3 * Hd, Hd, 512);
    gemm_h16<1, 0, 0><<<dim3(24, 2, 2), 256, GH_SMEM>>>(hidden, nullptr, Hd, gru_Whh, nullptr,
                                                        part + 2L * B * 3 * Hd, nullptr,
                                                        3 * Hd, Hd, 512);
    gru_fuse<<<(B * Hd + 255) / 256, 256>>>(part, hidden, gru_bih, gru_bhh, out_h);

    // 6. logits -> out_logp directly, bare exp-sum partials fused in epilogue
    gemm_h16<1, 0, 2><<<dim3(NTV, 2, 1), 256, GH_SMEM>>>(out_h, nullptr, Hd, out_W, out_b,
                                                         out_logp, rsum, V, Hd, Hd);

    // 7. lse (parallel, plain sum) + in-place subtract
    lse_reduce<<<B, 128>>>(rsum, lse);
    logp_sub<<<dim3(50, B), 1024>>>(out_logp, lse);
}

// round 10
// speedup vs baseline: 1.7572x; 1.1410x over previous
#include <cuda_runtime.h>
#include <cuda_fp16.h>
#include <math.h>
#include <stdint.h>

// Problem constants
#define B   256
#define Hd  1024
#define L   400
#define V   50257
#define NTV 393              // ceil(V/128)

#define OUT_H    ((long)B * V)
#define OUT_AW   ((long)B * V + (long)B * Hd)

// ---------------- scratch (device globals) ---------------------------------
__device__ float g_scores[B * L];
__device__ float g_attn[B * Hd];
__device__ float g_o[B * Hd];
__device__ float g_part[4L * B * 3 * Hd];     // split-K partials [4][B][3H]
__device__ float g_rsum[(long)B * NTV];       // [row][tile] exp-sums
__device__ float g_lse[B];
__device__ __half g_w16[(long)V * Hd];        // fp16 out_W (103 MB)
__device__ __half g_h16[B * Hd];              // fp16 h_new

// ---------------- helpers ---------------------------------------------------
__device__ __forceinline__ uint32_t smem_u32(const void* p) {
    uint32_t a;
    asm("{ .reg .u64 t; cvta.to.shared.u64 t, %1; cvt.u32.u64 %0, t; }" : "=r"(a) : "l"(p));
    return a;
}

__device__ __forceinline__ uint32_t h2bits(float x, float y) {
    __half2 h = __floats2half2_rn(x, y);
    return *(uint32_t*)&h;
}

#define SWZ128(x) ((x) ^ (((x) >> 3) & 0x70))
#define SWZ64(x)  ((x) ^ (((x) >> 3) & 0x30))

__device__ __forceinline__ void ldsm_x4(uint32_t* r, uint32_t addr) {
    asm volatile("ldmatrix.sync.aligned.m8n8.x4.shared.b16 {%0,%1,%2,%3}, [%4];"
                 : "=r"(r[0]), "=r"(r[1]), "=r"(r[2]), "=r"(r[3]) : "r"(addr));
}

__device__ __forceinline__ void mma_f16(float* c, const uint32_t* a, const uint32_t* b) {
    asm volatile(
        "mma.sync.aligned.m16n8k16.row.col.f32.f16.f16.f32 "
        "{%0,%1,%2,%3}, {%4,%5,%6,%7}, {%8,%9}, {%0,%1,%2,%3};"
        : "+f"(c[0]), "+f"(c[1]), "+f"(c[2]), "+f"(c[3])
        : "r"(a[0]), "r"(a[1]), "r"(a[2]), "r"(a[3]), "r"(b[0]), "r"(b[1]));
}

// fast exp (full-rate FFMA path)
__device__ __forceinline__ float fexp(float x)
{
    float t = fmaxf(x * 1.44269504f, -125.0f);
    float fi = t + 12582912.f;
    int   i = __float_as_int(fi);
    float fr = t - (fi - 12582912.f);
    float y = fr * 0.69314718f;
    float p = fmaf(y, 0.25f, 1.f);
    p = fmaf(y * p, 0.33333333f, 1.f);
    p = fmaf(y * p, 0.5f, 1.f);
    p = fmaf(y, p, 1.f);
    return __int_as_float((i + (127 - 0x4B400000)) << 23) * p;
}

// ---------------- fp32→fp16 convert (8 elems/thread) -------------------------
__global__ void f2h_vec(const float* __restrict__ in, __half* __restrict__ out, long n)
{
    long i = ((long)blockIdx.x * blockDim.x + threadIdx.x) * 8;
    if (i >= n) return;
    float4 a = *(const float4*)(in + i);
    float4 b = *(const float4*)(in + i + 4);
    uint4 u;
    u.x = h2bits(a.x, a.y); u.y = h2bits(a.z, a.w);
    u.z = h2bits(b.x, b.y); u.w = h2bits(b.z, b.w);
    *(uint4*)(out + i) = u;
}

// ---------------- cp.async fp16 logits GEMM ---------------------------------
// out_logp[256,V] = h16[256,1024] @ w16[V,1024]^T + bias; fused exp-sums.
// grid (NTV, 2), 256 thr, BK=32, 4 stages x 16KB (A 8KB + B 8KB), SW64.
#define LG_SMEM 65536

__global__ __launch_bounds__(256, 2) void gemm_lg(
    const __half* __restrict__ A16, const __half* __restrict__ W16,
    const float* __restrict__ bias, float* __restrict__ C,
    float* __restrict__ rsum)
{
    extern __shared__ char smem[];
    const uint32_t sb = smem_u32(smem);
    const int N = V, K = Hd;

    const int t = threadIdx.x;
    const int lane = t & 31;
    const int wid = t >> 5;
    const int wm = wid >> 2;       // 0..1
    const int wn = wid & 3;        // 0..3
    const int g = lane >> 2;
    const int q = lane & 3;

    const int m0 = blockIdx.y * 128;
    const int n0 = blockIdx.x * 128;

    // loader: 512 16B-cells per 8KB tile, 2 per thread
    const int lrow = t >> 2;            // 0..63 (+64)
    const int lc16 = (t & 3) * 16;      // byte col in 64B row
    const int lc8  = (t & 3) * 8;       // half col

    float acc[4][4][4];
    #pragma unroll
    for (int i = 0; i < 4; i++)
        #pragma unroll
        for (int j = 0; j < 4; j++)
            #pragma unroll
            for (int v = 0; v < 4; v++) acc[i][j][v] = 0.f;

    auto issue_stage = [&](int s, int c) {
        const int k0 = c * 32;
        const uint32_t Ab = sb + s * 16384;
        const uint32_t Bb = Ab + 8192;
        #pragma unroll
        for (int i = 0; i < 2; i++) {
            int row = lrow + i * 64;
            const __half* src = A16 + (long)(m0 + row) * K + k0 + lc8;
            uint32_t dst = Ab + SWZ64((uint32_t)(row * 64 + lc16));
            asm volatile("cp.async.cg.shared.global [%0], [%1], 16;" :: "r"(dst), "l"(src));
        }
        #pragma unroll
        for (int i = 0; i < 2; i++) {
            int row = lrow + i * 64;
            int n = n0 + row;
            const __half* src = W16 + (long)n * K + k0 + lc8;
            uint32_t dst = Bb + SWZ64((uint32_t)(row * 64 + lc16));
            int bytes = (n < N) ? 16 : 0;
            asm volatile("cp.async.cg.shared.global [%0], [%1], 16, %2;"
                         :: "r"(dst), "l"(src), "r"(bytes));
        }
        asm volatile("cp.async.commit_group;" ::: "memory");
    };

    const int a_row = lane & 15;
    const int a_cb = (lane >> 4) << 4;
    const int b_row = (lane & 7) + ((lane >> 4) << 3);
    const int b_cb = ((lane >> 3) & 1) << 4;

    auto compute = [&](int s) {
        const uint32_t Ab = sb + s * 16384;
        const uint32_t Bb = Ab + 8192;
        #pragma unroll
        for (int ks = 0; ks < 2; ks++) {
            uint32_t af[4][4], bf[2][4];
            #pragma unroll
            for (int mt = 0; mt < 4; mt++) {
                int r = wm * 64 + mt * 16 + a_row;
                ldsm_x4(af[mt], Ab + SWZ64((uint32_t)(r * 64 + ks * 32 + a_cb)));
            }
            #pragma unroll
            for (int np = 0; np < 2; np++) {
                int r = wn * 32 + np * 16 + b_row;
                ldsm_x4(bf[np], Bb + SWZ64((uint32_t)(r * 64 + ks * 32 + b_cb)));
            }
            #pragma unroll
            for (int mt = 0; mt < 4; mt++)
                #pragma unroll
                for (int nt = 0; nt < 4; nt++)
                    mma_f16(acc[mt][nt], af[mt], &bf[nt >> 1][(nt & 1) * 2]);
        }
    };

    const int NCH = K / 32;   // 32
    issue_stage(0, 0); issue_stage(1, 1); issue_stage(2, 2);
    for (int c = 0; c < NCH; c++) {
        asm volatile("cp.async.wait_group 2;" ::: "memory");
        __syncthreads();
        compute(c & 3);
        if (c + 3 < NCH) issue_stage((c + 3) & 3, c + 3);
        else asm volatile("cp.async.commit_group;" ::: "memory");
    }

    // ---- epilogue: bias + store + bare exp-sum ----
    float se[4][2];
    #pragma unroll
    for (int mt = 0; mt < 4; mt++) { se[mt][0] = 0.f; se[mt][1] = 0.f; }
    #pragma unroll
    for (int mt = 0; mt < 4; mt++) {
        int row = m0 + wm * 64 + mt * 16 + g;
        #pragma unroll
        for (int nt = 0; nt < 4; nt++) {
            int col = n0 + wn * 32 + nt * 8 + 2 * q;
            float b0 = (col < N) ? bias[col] : 0.f;
            float b1 = (col + 1 < N) ? bias[col + 1] : 0.f;
            float v0 = acc[mt][nt][0] + b0, v1 = acc[mt][nt][1] + b1;
            float v2 = acc[mt][nt][2] + b0, v3 = acc[mt][nt][3] + b1;
            if (col < N)     { C[(long)row * N + col]           = v0; se[mt][0] += fexp(v0); }
            if (col + 1 < N) { C[(long)row * N + col + 1]       = v1; se[mt][0] += fexp(v1); }
            if (col < N)     { C[(long)(row + 8) * N + col]     = v2; se[mt][1] += fexp(v2); }
            if (col + 1 < N) { C[(long)(row + 8) * N + col + 1] = v3; se[mt][1] += fexp(v3); }
        }
    }
    float* reds = (float*)smem;
    __syncthreads();
    #pragma unroll
    for (int mt = 0; mt < 4; mt++) {
        #pragma unroll
        for (int half = 0; half < 2; half++) {
            float sv = se[mt][half];
            sv += __shfl_xor_sync(0xffffffff, sv, 1);
            sv += __shfl_xor_sync(0xffffffff, sv, 2);
            if (q == 0) {
                int rloc = wm * 64 + mt * 16 + g + half * 8;
                reds[wn * 128 + rloc] = sv;
            }
        }
    }
    __syncthreads();
    if (t < 128) {
        float s = reds[t] + reds[128 + t] + reds[256 + t] + reds[384 + t];
        rsum[(long)(m0 + t) * NTV + blockIdx.x] = s;
    }
}

// ---------------- fp16 tensor-core GEMM (R9 engine, small GEMMs) ------------
#define GH_SMEM 65536

template<int TRANSB, int CONCAT>
__global__ __launch_bounds__(256, 1) void gemm_h16(
    const float* __restrict__ A1, const float* __restrict__ A2, int KA1,
    const float* __restrict__ W,
    float* __restrict__ C, int N, int K, int chunkK)
{
    extern __shared__ char smem[];
    const uint32_t sb = smem_u32(smem);

    const int t = threadIdx.x;
    const int lane = t & 31;
    const int wid = t >> 5;
    const int wm = wid >> 2;
    const int wn = wid & 3;
    const int g = lane >> 2;
    const int q = lane & 3;

    const int m0 = blockIdx.y * 128;
    const int n0 = blockIdx.x * 128;
    const int kstart = blockIdx.z * chunkK;
    const int kend = min(kstart + chunkK, K);
    const int KA2 = K - KA1;

    const int arow = t >> 4;
    const int acol = (t & 15) * 4;

    float4 ra[8], rb[8];
    float4 rba[4], rbb[4];

    float acc[4][4][4];
    #pragma unroll
    for (int i = 0; i < 4; i++)
        #pragma unroll
        for (int j = 0; j < 4; j++)
            #pragma unroll
            for (int v = 0; v < 4; v++) acc[i][j][v] = 0.f;

    auto loadA = [&](int k0) {
        #pragma unroll
        for (int i = 0; i < 8; i++) {
            int m = m0 + arow + 16 * i;
            int k = k0 + acol;
            ra[i] = make_float4(0.f, 0.f, 0.f, 0.f);
            if (k < kend) {
                if constexpr (CONCAT) {
                    if (k < KA1) ra[i] = *(const float4*)&A1[(long)m * KA1 + k];
                    else         ra[i] = *(const float4*)&A2[(long)m * KA2 + (k - KA1)];
                } else {
                    ra[i] = *(const float4*)&A1[(long)m * K + k];
                }
            }
        }
    };
    auto loadB = [&](int k0) {
        if (TRANSB) {
            #pragma unroll
            for (int i = 0; i < 8; i++) {
                int n = n0 + arow + 16 * i;
                int k = k0 + acol;
                rb[i] = make_float4(0.f, 0.f, 0.f, 0.f);
                if (n < N && k < kend) rb[i] = *(const float4*)&W[(long)n * K + k];
            }
        } else {
            #pragma unroll
            for (int i = 0; i < 4; i++) {
                int cell = t + i * 256;
                int kp = cell >> 5;
                int nq = cell & 31;
                int k = k0 + 2 * kp;
                int n = n0 + nq * 4;
                rba[i] = make_float4(0.f, 0.f, 0.f, 0.f);
                rbb[i] = make_float4(0.f, 0.f, 0.f, 0.f);
                if (k < kend && n < N) {
                    rba[i] = *(const float4*)&W[(long)k * N + n];
                    if (k + 1 < kend) rbb[i] = *(const float4*)&W[(long)(k + 1) * N + n];
                }
            }
        }
    };
    auto storeAB = [&](int s) {
        char* Ab = smem + s * 32768;
        char* Bb = smem + s * 32768 + 16384;
        #pragma unroll
        for (int i = 0; i < 8; i++) {
            int row = arow + 16 * i;
            uint32_t off = SWZ128((uint32_t)(row * 128 + acol * 2));
            *(uint2*)(Ab + off) = make_uint2(h2bits(ra[i].x, ra[i].y), h2bits(ra[i].z, ra[i].w));
        }
        if (TRANSB) {
            #pragma unroll
            for (int i = 0; i < 8; i++) {
                int row = arow + 16 * i;
                uint32_t off = SWZ128((uint32_t)(row * 128 + acol * 2));
                *(uint2*)(Bb + off) = make_uint2(h2bits(rb[i].x, rb[i].y), h2bits(rb[i].z, rb[i].w));
            }
        } else {
            #pragma unroll
            for (int i = 0; i < 4; i++) {
                int cell = t + i * 256;
                int kp = cell >> 5;
                int nq = cell & 31;
                const float* fa = (const float*)&rba[i];
                const float* fb = (const float*)&rbb[i];
                #pragma unroll
                for (int j = 0; j < 4; j++) {
                    int row = nq * 4 + j;
                    uint32_t off = SWZ128((uint32_t)(row * 128 + kp * 4));
                    *(uint32_t*)(Bb + off) = h2bits(fa[j], fb[j]);
                }
            }
        }
    };

    const int a_row = lane & 15;
    const int a_cb = (lane >> 4) << 4;
    const int b_row = (lane & 7) + ((lane >> 4) << 3);
    const int b_cb = ((lane >> 3) & 1) << 4;

    auto compute = [&](int s) {
        const uint32_t Ab = sb + s * 32768;
        const uint32_t Bb = Ab + 16384;
        #pragma unroll
        for (int ks = 0; ks < 4; ks++) {
            uint32_t af[4][4], bf[2][4];
            #pragma unroll
            for (int mt = 0; mt < 4; mt++) {
                int r = wm * 64 + mt * 16 + a_row;
                ldsm_x4(af[mt], Ab + SWZ128((uint32_t)(r * 128 + ks * 32 + a_cb)));
            }
            #pragma unroll
            for (int np = 0; np < 2; np++) {
                int r = wn * 32 + np * 16 + b_row;
                ldsm_x4(bf[np], Bb + SWZ128((uint32_t)(r * 128 + ks * 32 + b_cb)));
            }
            #pragma unroll
            for (int mt = 0; mt < 4; mt++)
                #pragma unroll
                for (int nt = 0; nt < 4; nt++)
                    mma_f16(acc[mt][nt], af[mt], &bf[nt >> 1][(nt & 1) * 2]);
        }
    };

    const int ntiles = (kend - kstart + 63) / 64;

    loadA(kstart); loadB(kstart);
    storeAB(0);
    __syncthreads();
    for (int c = 1; c < ntiles; c++) {
        loadA(kstart + c * 64); loadB(kstart + c * 64);
        compute((c - 1) & 1);
        storeAB(c & 1);
        __syncthreads();
    }
    compute((ntiles - 1) & 1);

    float* Cw = C + (long)blockIdx.z * 256 * N;
    #pragma unroll
    for (int mt = 0; mt < 4; mt++) {
        int row = m0 + wm * 64 + mt * 16 + g;
        #pragma unroll
        for (int nt = 0; nt < 4; nt++) {
            int col = n0 + wn * 32 + nt * 8 + 2 * q;
            if (col < N)     Cw[(long)row * N + col]           = acc[mt][nt][0];
            if (col + 1 < N) Cw[(long)row * N + col + 1]       = acc[mt][nt][1];
            if (col < N)     Cw[(long)(row + 8) * N + col]     = acc[mt][nt][2];
            if (col + 1 < N) Cw[(long)(row + 8) * N + col + 1] = acc[mt][nt][3];
        }
    }
}

// ---------------- split-K reduce (+bias, +relu) — deterministic -------------
__global__ void reduce_bias(const float* __restrict__ part, const float* __restrict__ bias,
                            float* __restrict__ out, int MN, int N, int SK, int relu)
{
    int idx = blockIdx.x * blockDim.x + threadIdx.x;
    if (idx >= MN) return;
    float s = 0.f;
    for (int c = 0; c < SK; c++) s += part[(long)c * MN + idx];
    if (bias) s += bias[idx % N];
    if (relu) s = fmaxf(s, 0.f);
    out[idx] = s;
}

// ---------------- fused GRU: reduce + gates + dual fp32/fp16 h write --------
__global__ void gru_fuse(const float* __restrict__ part, const float* __restrict__ hidden,
                         const float* __restrict__ bih, const float* __restrict__ bhh,
                         float* __restrict__ h_new, __half* __restrict__ h16)
{
    int idx = blockIdx.x * blockDim.x + threadIdx.x;
    if (idx >= B * Hd) return;
    int b = idx / Hd, j = idx - b * Hd;
    const long NN = 3 * Hd;
    const long MN = (long)B * NN;
    const float* giA = part;
    const float* ghA = part + 2 * MN;
    long base = (long)b * NN + j;

    float ir = giA[base] + giA[MN + base] + bih[j];
    float iz = giA[base + Hd] + giA[MN + base + Hd] + bih[j + Hd];
    float in_ = giA[base + 2 * Hd] + giA[MN + base + 2 * Hd] + bih[j + 2 * Hd];
    float hr = ghA[base] + ghA[MN + base] + bhh[j];
    float hz = ghA[base + Hd] + ghA[MN + base + Hd] + bhh[j + Hd];
    float hn = ghA[base + 2 * Hd] + ghA[MN + base + 2 * Hd] + bhh[j + 2 * Hd];

    float r = 1.f / (1.f + expf(-(ir + hr)));
    float z = 1.f / (1.f + expf(-(iz + hz)));
    float nn = tanhf(in_ + r * hn);
    float h = (1.f - z) * nn + z * hidden[idx];
    h_new[idx] = h;
    h16[idx] = __float2half_rn(h);
}

// ---------------- warp-per-row softmax (L=400) -------------------------------
__global__ void softmax_warp(const float* __restrict__ in, float* __restrict__ out, int n)
{
    int w = (blockIdx.x * blockDim.x + threadIdx.x) >> 5;
    int lid = threadIdx.x & 31;
    if (w >= B) return;
    const float* x = in + (long)w * n;
    float* y = out + (long)w * n;

    float m = -1e30f;
    for (int i = lid; i < n; i += 32) m = fmaxf(m, x[i]);
    #pragma unroll
    for (int o = 16; o > 0; o >>= 1) m = fmaxf(m, __shfl_xor_sync(0xffffffff, m, o));
    float s = 0.f;
    for (int i = lid; i < n; i += 32) s += fexp(x[i] - m);
    #pragma unroll
    for (int o = 16; o > 0; o >>= 1) s += __shfl_xor_sync(0xffffffff, s, o);
    float inv = 1.f / s;
    for (int i = lid; i < n; i += 32) y[i] = fexp(x[i] - m) * inv;
}

// ---------------- parallel lse: one block per row, plain sum -----------------
__global__ void lse_reduce(const float* __restrict__ rsum, float* __restrict__ lse)
{
    int row = blockIdx.x;
    int t = threadIdx.x;   // 128
    float s = 0.f;
    for (int tile = t; tile < NTV; tile += 128) s += rsum[(long)row * NTV + tile];
    #pragma unroll
    for (int o = 16; o > 0; o >>= 1) s += __shfl_xor_sync(0xffffffff, s, o);
    __shared__ float ss[4];
    if ((t & 31) == 0) ss[t >> 5] = s;
    __syncthreads();
    if (t == 0) lse[row] = logf(ss[0] + ss[1] + ss[2] + ss[3]);
}

// ---------------- final: logp -= lse (in place) ------------------------------
__global__ void logp_sub(float* __restrict__ logp, const float* __restrict__ lse)
{
    int col = blockIdx.x * 1024 + threadIdx.x;
    int row = blockIdx.y;
    if (col < V) logp[(long)row * V + col] -= lse[row];
}

// ---------------- launch -----------------------------------------------------
extern "C" void kernel_launch(void* const* d_in, const int* in_sizes, int n_in,
                              void* d_out, int out_size)
{
    const float* embedded = (const float*)d_in[0];
    const float* hidden   = (const float*)d_in[1];
    const float* enc      = (const float*)d_in[2];
    const float* attn_W   = (const float*)d_in[3];
    const float* attn_b   = (const float*)d_in[4];
    const float* comb_W   = (const float*)d_in[5];
    const float* comb_b   = (const float*)d_in[6];
    const float* gru_Wih  = (const float*)d_in[7];
    const float* gru_Whh  = (const float*)d_in[8];
    const float* gru_bih  = (const float*)d_in[9];
    const float* gru_bhh  = (const float*)d_in[10];
    const float* out_W    = (const float*)d_in[11];
    const float* out_b    = (const float*)d_in[12];

    float* out = (float*)d_out;
    float* out_logp = out;
    float* out_h    = out + OUT_H;
    float* out_aw   = out + OUT_AW;

    float *scores, *attn, *o, *part, *rsum, *lse;
    __half *w16, *h16;
    cudaGetSymbolAddress((void**)&scores, g_scores);
    cudaGetSymbolAddress((void**)&attn, g_attn);
    cudaGetSymbolAddress((void**)&o, g_o);
    cudaGetSymbolAddress((void**)&part, g_part);
    cudaGetSymbolAddress((void**)&rsum, g_rsum);
    cudaGetSymbolAddress((void**)&lse, g_lse);
    cudaGetSymbolAddress((void**)&w16, g_w16);
    cudaGetSymbolAddress((void**)&h16, g_h16);

    cudaFuncSetAttribute((const void*)gemm_h16<1, 1>, cudaFuncAttributeMaxDynamicSharedMemorySize, GH_SMEM);
    cudaFuncSetAttribute((const void*)gemm_h16<1, 0>, cudaFuncAttributeMaxDynamicSharedMemorySize, GH_SMEM);
    cudaFuncSetAttribute((const void*)gemm_h16<0, 0>, cudaFuncAttributeMaxDynamicSharedMemorySize, GH_SMEM);
    cudaFuncSetAttribute((const void*)gemm_lg, cudaFuncAttributeMaxDynamicSharedMemorySize, LG_SMEM);

    // 0. convert out_W to fp16 (51,463,168 elems, 8/thread)
    f2h_vec<<<(int)(((long)V * Hd / 8 + 255) / 256), 256>>>(out_W, w16, (long)V * Hd);

    // 1. scores = [x|h] @ attn_W^T (+attn_b), split-K=8
    gemm_h16<1, 1><<<dim3(4, 2, 8), 256, GH_SMEM>>>(embedded, hidden, Hd, attn_W,
                                                    part, L, 2 * Hd, 256);
    reduce_bias<<<(B * L + 255) / 256, 256>>>(part, attn_b, scores, B * L, L, 8, 0);

    // 2. attn_weights = softmax(scores) -> out_aw
    softmax_warp<<<32, 256>>>(scores, out_aw, L);

    // 3. attn_applied = attn_weights @ enc (NN), split-K=4
    gemm_h16<0, 0><<<dim3(8, 2, 4), 256, GH_SMEM>>>(out_aw, nullptr, L, enc,
                                                    part, Hd, L, 128);
    reduce_bias<<<(B * Hd + 255) / 256, 256>>>(part, nullptr, attn, B * Hd, Hd, 4, 0);

    // 4. o = relu([x|attn] @ comb_W^T + comb_b), split-K=4
    gemm_h16<1, 1><<<dim3(8, 2, 4), 256, GH_SMEM>>>(embedded, attn, Hd, comb_W,
                                                    part, Hd, 2 * Hd, 512);
    reduce_bias<<<(B * Hd + 255) / 256, 256>>>(part, comb_b, o, B * Hd, Hd, 4, 1);

    // 5. gi / gh split-K=2 each, fused gates + fp16 h
    gemm_h16<1, 0><<<dim3(24, 2, 2), 256, GH_SMEM>>>(o, nullptr, Hd, gru_Wih,
                                                     part, 3 * Hd, Hd, 512);
    gemm_h16<1, 0><<<dim3(24, 2, 2), 256, GH_SMEM>>>(hidden, nullptr, Hd, gru_Whh,
                                                     part + 2L * B * 3 * Hd, 3 * Hd, Hd, 512);
    gru_fuse<<<(B * Hd + 255) / 256, 256>>>(part, hidden, gru_bih, gru_bhh, out_h, h16);

    // 6. logits -> out_logp, cp.async fp16 engine, exp-sum partials fused
    gemm_lg<<<dim3(NTV, 2), 256, LG_SMEM>>>(h16, w16, out_b, out_logp, rsum);

    // 7. lse + in-place subtract
    lse_reduce<<<B, 128>>>(rsum, lse);
    logp_sub<<<dim3(50, B), 1024>>>(out_logp, lse);
}

// round 11
// speedup vs baseline: 1.8638x; 1.0607x over previous
#include <cuda_runtime.h>
#include <cuda_fp16.h>
#include <math.h>
#include <stdint.h>

// Problem constants
#define B   256
#define Hd  1024
#define L   400
#define V   50257
#define NTV 393              // ceil(V/128)

#define OUT_H    ((long)B * V)
#define OUT_AW   ((long)B * V + (long)B * Hd)

// ---------------- scratch (device globals) ---------------------------------
__device__ float g_scores[B * L];
__device__ float g_attn[B * Hd];
__device__ float g_o[B * Hd];
__device__ float g_part[4L * B * 3 * Hd];     // split-K partials [4][B][3H]
__device__ float g_rsum[(long)B * NTV];       // [row][tile] exp-sums
__device__ float g_lse[B];
__device__ __half g_w16[(long)V * Hd];        // fp16 out_W (103 MB)
__device__ __half g_h16[B * Hd];              // fp16 h_new

// ---------------- helpers ---------------------------------------------------
__device__ __forceinline__ uint32_t smem_u32(const void* p) {
    uint32_t a;
    asm("{ .reg .u64 t; cvta.to.shared.u64 t, %1; cvt.u32.u64 %0, t; }" : "=r"(a) : "l"(p));
    return a;
}

__device__ __forceinline__ uint32_t h2bits(float x, float y) {
    __half2 h = __floats2half2_rn(x, y);
    return *(uint32_t*)&h;
}

#define SWZ128(x) ((x) ^ (((x) >> 3) & 0x70))
#define SWZ64(x)  ((x) ^ (((x) >> 3) & 0x30))

__device__ __forceinline__ void ldsm_x4(uint32_t* r, uint32_t addr) {
    asm volatile("ldmatrix.sync.aligned.m8n8.x4.shared.b16 {%0,%1,%2,%3}, [%4];"
                 : "=r"(r[0]), "=r"(r[1]), "=r"(r[2]), "=r"(r[3]) : "r"(addr));
}

__device__ __forceinline__ void mma_f16(float* c, const uint32_t* a, const uint32_t* b) {
    asm volatile(
        "mma.sync.aligned.m16n8k16.row.col.f32.f16.f16.f32 "
        "{%0,%1,%2,%3}, {%4,%5,%6,%7}, {%8,%9}, {%0,%1,%2,%3};"
        : "+f"(c[0]), "+f"(c[1]), "+f"(c[2]), "+f"(c[3])
        : "r"(a[0]), "r"(a[1]), "r"(a[2]), "r"(a[3]), "r"(b[0]), "r"(b[1]));
}

// fast exp (full-rate FFMA path)
__device__ __forceinline__ float fexp(float x)
{
    float t = fmaxf(x * 1.44269504f, -125.0f);
    float fi = t + 12582912.f;
    int   i = __float_as_int(fi);
    float fr = t - (fi - 12582912.f);
    float y = fr * 0.69314718f;
    float p = fmaf(y, 0.25f, 1.f);
    p = fmaf(y * p, 0.33333333f, 1.f);
    p = fmaf(y * p, 0.5f, 1.f);
    p = fmaf(y, p, 1.f);
    return __int_as_float((i + (127 - 0x4B400000)) << 23) * p;
}

// ---------------- fp32→fp16 convert (8 elems/thread) -------------------------
__global__ void f2h_vec(const float* __restrict__ in, __half* __restrict__ out, long n)
{
    long i = ((long)blockIdx.x * blockDim.x + threadIdx.x) * 8;
    if (i >= n) return;
    float4 a = *(const float4*)(in + i);
    float4 b = *(const float4*)(in + i + 4);
    uint4 u;
    u.x = h2bits(a.x, a.y); u.y = h2bits(a.z, a.w);
    u.z = h2bits(b.x, b.y); u.w = h2bits(b.z, b.w);
    *(uint4*)(out + i) = u;
}

// ---------------- cp.async fp16 logits GEMM ---------------------------------
// out_logp[256,V] = h16[256,1024] @ w16[V,1024]^T + bias; fused exp-sums.
// grid (NTV, 2), 256 thr, BK=32, 4 stages x 16KB (A 8KB + B 8KB), SW64.
#define LG_SMEM 65536

__global__ __launch_bounds__(256, 2) void gemm_lg(
    const __half* __restrict__ A16, const __half* __restrict__ W16,
    const float* __restrict__ bias, float* __restrict__ C,
    float* __restrict__ rsum)
{
    extern __shared__ char smem[];
    const uint32_t sb = smem_u32(smem);
    const int N = V, K = Hd;

    const int t = threadIdx.x;
    const int lane = t & 31;
    const int wid = t >> 5;
    const int wm = wid >> 2;       // 0..1
    const int wn = wid & 3;        // 0..3
    const int g = lane >> 2;
    const int q = lane & 3;

    const int m0 = blockIdx.y * 128;
    const int n0 = blockIdx.x * 128;

    const int lrow = t >> 2;            // 0..63 (+64)
    const int lc16 = (t & 3) * 16;      // byte col in 64B row
    const int lc8  = (t & 3) * 8;       // half col

    float acc[4][4][4];
    #pragma unroll
    for (int i = 0; i < 4; i++)
        #pragma unroll
        for (int j = 0; j < 4; j++)
            #pragma unroll
            for (int v = 0; v < 4; v++) acc[i][j][v] = 0.f;

    auto issue_stage = [&](int s, int c) {
        const int k0 = c * 32;
        const uint32_t Ab = sb + s * 16384;
        const uint32_t Bb = Ab + 8192;
        #pragma unroll
        for (int i = 0; i < 2; i++) {
            int row = lrow + i * 64;
            const __half* src = A16 + (long)(m0 + row) * K + k0 + lc8;
            uint32_t dst = Ab + SWZ64((uint32_t)(row * 64 + lc16));
            asm volatile("cp.async.cg.shared.global [%0], [%1], 16;" :: "r"(dst), "l"(src));
        }
        #pragma unroll
        for (int i = 0; i < 2; i++) {
            int row = lrow + i * 64;
            int n = n0 + row;
            const __half* src = W16 + (long)n * K + k0 + lc8;
            uint32_t dst = Bb + SWZ64((uint32_t)(row * 64 + lc16));
            int bytes = (n < N) ? 16 : 0;
            asm volatile("cp.async.cg.shared.global [%0], [%1], 16, %2;"
                         :: "r"(dst), "l"(src), "r"(bytes));
        }
        asm volatile("cp.async.commit_group;" ::: "memory");
    };

    const int a_row = lane & 15;
    const int a_cb = (lane >> 4) << 4;
    const int b_row = (lane & 7) + ((lane >> 4) << 3);
    const int b_cb = ((lane >> 3) & 1) << 4;

    auto compute = [&](int s) {
        const uint32_t Ab = sb + s * 16384;
        const uint32_t Bb = Ab + 8192;
        #pragma unroll
        for (int ks = 0; ks < 2; ks++) {
            uint32_t af[4][4], bf[2][4];
            #pragma unroll
            for (int mt = 0; mt < 4; mt++) {
                int r = wm * 64 + mt * 16 + a_row;
                ldsm_x4(af[mt], Ab + SWZ64((uint32_t)(r * 64 + ks * 32 + a_cb)));
            }
            #pragma unroll
            for (int np = 0; np < 2; np++) {
                int r = wn * 32 + np * 16 + b_row;
                ldsm_x4(bf[np], Bb + SWZ64((uint32_t)(r * 64 + ks * 32 + b_cb)));
            }
            #pragma unroll
            for (int mt = 0; mt < 4; mt++)
                #pragma unroll
                for (int nt = 0; nt < 4; nt++)
                    mma_f16(acc[mt][nt], af[mt], &bf[nt >> 1][(nt & 1) * 2]);
        }
    };

    const int NCH = K / 32;   // 32
    issue_stage(0, 0); issue_stage(1, 1); issue_stage(2, 2);
    for (int c = 0; c < NCH; c++) {
        asm volatile("cp.async.wait_group 2;" ::: "memory");
        __syncthreads();
        compute(c & 3);
        if (c + 3 < NCH) issue_stage((c + 3) & 3, c + 3);
        else asm volatile("cp.async.commit_group;" ::: "memory");
    }

    // ---- epilogue: bias + store + bare exp-sum ----
    float se[4][2];
    #pragma unroll
    for (int mt = 0; mt < 4; mt++) { se[mt][0] = 0.f; se[mt][1] = 0.f; }
    #pragma unroll
    for (int mt = 0; mt < 4; mt++) {
        int row = m0 + wm * 64 + mt * 16 + g;
        #pragma unroll
        for (int nt = 0; nt < 4; nt++) {
            int col = n0 + wn * 32 + nt * 8 + 2 * q;
            float b0 = (col < N) ? bias[col] : 0.f;
            float b1 = (col + 1 < N) ? bias[col + 1] : 0.f;
            float v0 = acc[mt][nt][0] + b0, v1 = acc[mt][nt][1] + b1;
            float v2 = acc[mt][nt][2] + b0, v3 = acc[mt][nt][3] + b1;
            if (col < N)     { C[(long)row * N + col]           = v0; se[mt][0] += fexp(v0); }
            if (col + 1 < N) { C[(long)row * N + col + 1]       = v1; se[mt][0] += fexp(v1); }
            if (col < N)     { C[(long)(row + 8) * N + col]     = v2; se[mt][1] += fexp(v2); }
            if (col + 1 < N) { C[(long)(row + 8) * N + col + 1] = v3; se[mt][1] += fexp(v3); }
        }
    }
    float* reds = (float*)smem;
    __syncthreads();
    #pragma unroll
    for (int mt = 0; mt < 4; mt++) {
        #pragma unroll
        for (int half = 0; half < 2; half++) {
            float sv = se[mt][half];
            sv += __shfl_xor_sync(0xffffffff, sv, 1);
            sv += __shfl_xor_sync(0xffffffff, sv, 2);
            if (q == 0) {
                int rloc = wm * 64 + mt * 16 + g + half * 8;
                reds[wn * 128 + rloc] = sv;
            }
        }
    }
    __syncthreads();
    if (t < 128) {
        float s = reds[t] + reds[128 + t] + reds[256 + t] + reds[384 + t];
        rsum[(long)(m0 + t) * NTV + blockIdx.x] = s;
    }
}

// ---------------- fp16 tensor-core GEMM (R9 engine, small GEMMs) ------------
#define GH_SMEM 65536

template<int TRANSB, int CONCAT>
__global__ __launch_bounds__(256, 1) void gemm_h16(
    const float* __restrict__ A1, const float* __restrict__ A2, int KA1,
    const float* __restrict__ W,
    float* __restrict__ C, int N, int K, int chunkK)
{
    extern __shared__ char smem[];
    const uint32_t sb = smem_u32(smem);

    const int t = threadIdx.x;
    const int lane = t & 31;
    const int wid = t >> 5;
    const int wm = wid >> 2;
    const int wn = wid & 3;
    const int g = lane >> 2;
    const int q = lane & 3;

    const int m0 = blockIdx.y * 128;
    const int n0 = blockIdx.x * 128;
    const int kstart = blockIdx.z * chunkK;
    const int kend = min(kstart + chunkK, K);
    const int KA2 = K - KA1;

    const int arow = t >> 4;
    const int acol = (t & 15) * 4;

    float4 ra[8], rb[8];
    float4 rba[4], rbb[4];

    float acc[4][4][4];
    #pragma unroll
    for (int i = 0; i < 4; i++)
        #pragma unroll
        for (int j = 0; j < 4; j++)
            #pragma unroll
            for (int v = 0; v < 4; v++) acc[i][j][v] = 0.f;

    auto loadA = [&](int k0) {
        #pragma unroll
        for (int i = 0; i < 8; i++) {
            int m = m0 + arow + 16 * i;
            int k = k0 + acol;
            ra[i] = make_float4(0.f, 0.f, 0.f, 0.f);
            if (k < kend) {
                if constexpr (CONCAT) {
                    if (k < KA1) ra[i] = *(const float4*)&A1[(long)m * KA1 + k];
                    else         ra[i] = *(const float4*)&A2[(long)m * KA2 + (k - KA1)];
                } else {
                    ra[i] = *(const float4*)&A1[(long)m * K + k];
                }
            }
        }
    };
    auto loadB = [&](int k0) {
        if (TRANSB) {
            #pragma unroll
            for (int i = 0; i < 8; i++) {
                int n = n0 + arow + 16 * i;
                int k = k0 + acol;
                rb[i] = make_float4(0.f, 0.f, 0.f, 0.f);
                if (n < N && k < kend) rb[i] = *(const float4*)&W[(long)n * K + k];
            }
        } else {
            #pragma unroll
            for (int i = 0; i < 4; i++) {
                int cell = t + i * 256;
                int kp = cell >> 5;
                int nq = cell & 31;
                int k = k0 + 2 * kp;
                int n = n0 + nq * 4;
                rba[i] = make_float4(0.f, 0.f, 0.f, 0.f);
                rbb[i] = make_float4(0.f, 0.f, 0.f, 0.f);
                if (k < kend && n < N) {
                    rba[i] = *(const float4*)&W[(long)k * N + n];
                    if (k + 1 < kend) rbb[i] = *(const float4*)&W[(long)(k + 1) * N + n];
                }
            }
        }
    };
    auto storeAB = [&](int s) {
        char* Ab = smem + s * 32768;
        char* Bb = smem + s * 32768 + 16384;
        #pragma unroll
        for (int i = 0; i < 8; i++) {
            int row = arow + 16 * i;
            uint32_t off = SWZ128((uint32_t)(row * 128 + acol * 2));
            *(uint2*)(Ab + off) = make_uint2(h2bits(ra[i].x, ra[i].y), h2bits(ra[i].z, ra[i].w));
        }
        if (TRANSB) {
            #pragma unroll
            for (int i = 0; i < 8; i++) {
                int row = arow + 16 * i;
                uint32_t off = SWZ128((uint32_t)(row * 128 + acol * 2));
                *(uint2*)(Bb + off) = make_uint2(h2bits(rb[i].x, rb[i].y), h2bits(rb[i].z, rb[i].w));
            }
        } else {
            #pragma unroll
            for (int i = 0; i < 4; i++) {
                int cell = t + i * 256;
                int kp = cell >> 5;
                int nq = cell & 31;
                const float* fa = (const float*)&rba[i];
                const float* fb = (const float*)&rbb[i];
                #pragma unroll
                for (int j = 0; j < 4; j++) {
                    int row = nq * 4 + j;
                    uint32_t off = SWZ128((uint32_t)(row * 128 + kp * 4));
                    *(uint32_t*)(Bb + off) = h2bits(fa[j], fb[j]);
                }
            }
        }
    };

    const int a_row = lane & 15;
    const int a_cb = (lane >> 4) << 4;
    const int b_row = (lane & 7) + ((lane >> 4) << 3);
    const int b_cb = ((lane >> 3) & 1) << 4;

    auto compute = [&](int s) {
        const uint32_t Ab = sb + s * 32768;
        const uint32_t Bb = Ab + 16384;
        #pragma unroll
        for (int ks = 0; ks < 4; ks++) {
            uint32_t af[4][4], bf[2][4];
            #pragma unroll
            for (int mt = 0; mt < 4; mt++) {
                int r = wm * 64 + mt * 16 + a_row;
                ldsm_x4(af[mt], Ab + SWZ128((uint32_t)(r * 128 + ks * 32 + a_cb)));
            }
            #pragma unroll
            for (int np = 0; np < 2; np++) {
                int r = wn * 32 + np * 16 + b_row;
                ldsm_x4(bf[np], Bb + SWZ128((uint32_t)(r * 128 + ks * 32 + b_cb)));
            }
            #pragma unroll
            for (int mt = 0; mt < 4; mt++)
                #pragma unroll
                for (int nt = 0; nt < 4; nt++)
                    mma_f16(acc[mt][nt], af[mt], &bf[nt >> 1][(nt & 1) * 2]);
        }
    };

    const int ntiles = (kend - kstart + 63) / 64;

    loadA(kstart); loadB(kstart);
    storeAB(0);
    __syncthreads();
    for (int c = 1; c < ntiles; c++) {
        loadA(kstart + c * 64); loadB(kstart + c * 64);
        compute((c - 1) & 1);
        storeAB(c & 1);
        __syncthreads();
    }
    compute((ntiles - 1) & 1);

    float* Cw = C + (long)blockIdx.z * 256 * N;
    #pragma unroll
    for (int mt = 0; mt < 4; mt++) {
        int row = m0 + wm * 64 + mt * 16 + g;
        #pragma unroll
        for (int nt = 0; nt < 4; nt++) {
            int col = n0 + wn * 32 + nt * 8 + 2 * q;
            if (col < N)     Cw[(long)row * N + col]           = acc[mt][nt][0];
            if (col + 1 < N) Cw[(long)row * N + col + 1]       = acc[mt][nt][1];
            if (col < N)     Cw[(long)(row + 8) * N + col]     = acc[mt][nt][2];
            if (col + 1 < N) Cw[(long)(row + 8) * N + col + 1] = acc[mt][nt][3];
        }
    }
}

// ---------------- split-K reduce (+bias, +relu) — deterministic -------------
__global__ void reduce_bias(const float* __restrict__ part, const float* __restrict__ bias,
                            float* __restrict__ out, int MN, int N, int SK, int relu)
{
    int idx = blockIdx.x * blockDim.x + threadIdx.x;
    if (idx >= MN) return;
    float s = 0.f;
    for (int c = 0; c < SK; c++) s += part[(long)c * MN + idx];
    if (bias) s += bias[idx % N];
    if (relu) s = fmaxf(s, 0.f);
    out[idx] = s;
}

// ---------------- fused GRU: reduce + gates + dual fp32/fp16 h write --------
__global__ void gru_fuse(const float* __restrict__ part, const float* __restrict__ hidden,
                         const float* __restrict__ bih, const float* __restrict__ bhh,
                         float* __restrict__ h_new, __half* __restrict__ h16)
{
    int idx = blockIdx.x * blockDim.x + threadIdx.x;
    if (idx >= B * Hd) return;
    int b = idx / Hd, j = idx - b * Hd;
    const long NN = 3 * Hd;
    const long MN = (long)B * NN;
    const float* giA = part;
    const float* ghA = part + 2 * MN;
    long base = (long)b * NN + j;

    float ir = giA[base] + giA[MN + base] + bih[j];
    float iz = giA[base + Hd] + giA[MN + base + Hd] + bih[j + Hd];
    float in_ = giA[base + 2 * Hd] + giA[MN + base + 2 * Hd] + bih[j + 2 * Hd];
    float hr = ghA[base] + ghA[MN + base] + bhh[j];
    float hz = ghA[base + Hd] + ghA[MN + base + Hd] + bhh[j + Hd];
    float hn = ghA[base + 2 * Hd] + ghA[MN + base + 2 * Hd] + bhh[j + 2 * Hd];

    float r = 1.f / (1.f + expf(-(ir + hr)));
    float z = 1.f / (1.f + expf(-(iz + hz)));
    float nn = tanhf(in_ + r * hn);
    float h = (1.f - z) * nn + z * hidden[idx];
    h_new[idx] = h;
    h16[idx] = __float2half_rn(h);
}

// ---------------- warp-per-row softmax (L=400) -------------------------------
__global__ void softmax_warp(const float* __restrict__ in, float* __restrict__ out, int n)
{
    int w = (blockIdx.x * blockDim.x + threadIdx.x) >> 5;
    int lid = threadIdx.x & 31;
    if (w >= B) return;
    const float* x = in + (long)w * n;
    float* y = out + (long)w * n;

    float m = -1e30f;
    for (int i = lid; i < n; i += 32) m = fmaxf(m, x[i]);
    #pragma unroll
    for (int o = 16; o > 0; o >>= 1) m = fmaxf(m, __shfl_xor_sync(0xffffffff, m, o));
    float s = 0.f;
    for (int i = lid; i < n; i += 32) s += fexp(x[i] - m);
    #pragma unroll
    for (int o = 16; o > 0; o >>= 1) s += __shfl_xor_sync(0xffffffff, s, o);
    float inv = 1.f / s;
    for (int i = lid; i < n; i += 32) y[i] = fexp(x[i] - m) * inv;
}

// ---------------- parallel lse: one block per row, plain sum -----------------
__global__ void lse_reduce(const float* __restrict__ rsum, float* __restrict__ lse)
{
    int row = blockIdx.x;
    int t = threadIdx.x;   // 128
    float s = 0.f;
    for (int tile = t; tile < NTV; tile += 128) s += rsum[(long)row * NTV + tile];
    #pragma unroll
    for (int o = 16; o > 0; o >>= 1) s += __shfl_xor_sync(0xffffffff, s, o);
    __shared__ float ss[4];
    if ((t & 31) == 0) ss[t >> 5] = s;
    __syncthreads();
    if (t == 0) lse[row] = logf(ss[0] + ss[1] + ss[2] + ss[3]);
}

// ---------------- final: logp -= lse (in place) ------------------------------
__global__ void logp_sub(float* __restrict__ logp, const float* __restrict__ lse)
{
    int col = blockIdx.x * 1024 + threadIdx.x;
    int row = blockIdx.y;
    if (col < V) logp[(long)row * V + col] -= lse[row];
}

// ---------------- launch -----------------------------------------------------
extern "C" void kernel_launch(void* const* d_in, const int* in_sizes, int n_in,
                              void* d_out, int out_size)
{
    const float* embedded = (const float*)d_in[0];
    const float* hidden   = (const float*)d_in[1];
    const float* enc      = (const float*)d_in[2];
    const float* attn_W   = (const float*)d_in[3];
    const float* attn_b   = (const float*)d_in[4];
    const float* comb_W   = (const float*)d_in[5];
    const float* comb_b   = (const float*)d_in[6];
    const float* gru_Wih  = (const float*)d_in[7];
    const float* gru_Whh  = (const float*)d_in[8];
    const float* gru_bih  = (const float*)d_in[9];
    const float* gru_bhh  = (const float*)d_in[10];
    const float* out_W    = (const float*)d_in[11];
    const float* out_b    = (const float*)d_in[12];

    float* out = (float*)d_out;
    float* out_logp = out;
    float* out_h    = out + OUT_H;
    float* out_aw   = out + OUT_AW;

    float *scores, *attn, *o, *part, *rsum, *lse;
    __half *w16, *h16;
    cudaGetSymbolAddress((void**)&scores, g_scores);
    cudaGetSymbolAddress((void**)&attn, g_attn);
    cudaGetSymbolAddress((void**)&o, g_o);
    cudaGetSymbolAddress((void**)&part, g_part);
    cudaGetSymbolAddress((void**)&rsum, g_rsum);
    cudaGetSymbolAddress((void**)&lse, g_lse);
    cudaGetSymbolAddress((void**)&w16, g_w16);
    cudaGetSymbolAddress((void**)&h16, g_h16);

    // one-time stream/event setup (host-side objects only; the captured graph
    // is identical on every call)
    static cudaStream_t sW = nullptr, sG = nullptr;
    static cudaEvent_t evFork, evW, evG;
    if (sW == nullptr) {
        cudaStreamCreateWithFlags(&sW, cudaStreamNonBlocking);
        cudaStreamCreateWithFlags(&sG, cudaStreamNonBlocking);
        cudaEventCreateWithFlags(&evFork, cudaEventDisableTiming);
        cudaEventCreateWithFlags(&evW, cudaEventDisableTiming);
        cudaEventCreateWithFlags(&evG, cudaEventDisableTiming);
    }

    cudaFuncSetAttribute((const void*)gemm_h16<1, 1>, cudaFuncAttributeMaxDynamicSharedMemorySize, GH_SMEM);
    cudaFuncSetAttribute((const void*)gemm_h16<1, 0>, cudaFuncAttributeMaxDynamicSharedMemorySize, GH_SMEM);
    cudaFuncSetAttribute((const void*)gemm_h16<0, 0>, cudaFuncAttributeMaxDynamicSharedMemorySize, GH_SMEM);
    cudaFuncSetAttribute((const void*)gemm_lg, cudaFuncAttributeMaxDynamicSharedMemorySize, LG_SMEM);

    // ---- fork: out_W conversion (stream sW) + gh GEMM (stream sG) ----
    cudaEventRecord(evFork, 0);

    cudaStreamWaitEvent(sW, evFork, 0);
    f2h_vec<<<(int)(((long)V * Hd / 8 + 255) / 256), 256, 0, sW>>>(out_W, w16, (long)V * Hd);
    cudaEventRecord(evW, sW);

    // gh = hidden @ Whh^T depends only on inputs; partials region
    // [2*MN, 4*MN) is disjoint from everything the main chain writes (< 2*MN).
    cudaStreamWaitEvent(sG, evFork, 0);
    gemm_h16<1, 0><<<dim3(24, 2, 2), 256, GH_SMEM, sG>>>(hidden, nullptr, Hd, gru_Whh,
                                                         part + 2L * B * 3 * Hd, 3 * Hd, Hd, 512);
    cudaEventRecord(evG, sG);

    // ---- main chain (legacy stream) ----
    // 1. scores = [x|h] @ attn_W^T (+attn_b), split-K=8
    gemm_h16<1, 1><<<dim3(4, 2, 8), 256, GH_SMEM>>>(embedded, hidden, Hd, attn_W,
                                                    part, L, 2 * Hd, 256);
    reduce_bias<<<(B * L + 255) / 256, 256>>>(part, attn_b, scores, B * L, L, 8, 0);

    // 2. attn_weights = softmax(scores) -> out_aw
    softmax_warp<<<32, 256>>>(scores, out_aw, L);

    // 3. attn_applied = attn_weights @ enc (NN), split-K=4
    gemm_h16<0, 0><<<dim3(8, 2, 4), 256, GH_SMEM>>>(out_aw, nullptr, L, enc,
                                                    part, Hd, L, 128);
    reduce_bias<<<(B * Hd + 255) / 256, 256>>>(part, nullptr, attn, B * Hd, Hd, 4, 0);

    // 4. o = relu([x|attn] @ comb_W^T + comb_b), split-K=4
    gemm_h16<1, 1><<<dim3(8, 2, 4), 256, GH_SMEM>>>(embedded, attn, Hd, comb_W,
                                                    part, Hd, 2 * Hd, 512);
    reduce_bias<<<(B * Hd + 255) / 256, 256>>>(part, comb_b, o, B * Hd, Hd, 4, 1);

    // 5. gi = o @ Wih^T split-K=2; join gh; fused gates + fp16 h
    gemm_h16<1, 0><<<dim3(24, 2, 2), 256, GH_SMEM>>>(o, nullptr, Hd, gru_Wih,
                                                     part, 3 * Hd, Hd, 512);
    cudaStreamWaitEvent(0, evG, 0);
    gru_fuse<<<(B * Hd + 255) / 256, 256>>>(part, hidden, gru_bih, gru_bhh, out_h, h16);

    // 6. join w16; logits -> out_logp, cp.async fp16 engine, exp-sum fused
    cudaStreamWaitEvent(0, evW, 0);
    gemm_lg<<<dim3(NTV, 2), 256, LG_SMEM>>>(h16, w16, out_b, out_logp, rsum);

    // 7. lse + in-place subtract
    lse_reduce<<<B, 128>>>(rsum, lse);
    logp_sub<<<dim3(50, B), 1024>>>(out_logp, lse);
}